// round 10
// baseline (speedup 1.0000x reference)
#include <cuda_runtime.h>
#include <cuda_bf16.h>
#include <cstdint>
#include <vector>
#include <algorithm>

// ---------------- problem constants ----------------
#define B_    8
#define S_    4096
#define D_    512
#define QT    128
#define NTH   256
#define NDEP  8

// smem byte offsets (dynamic smem base AB)
// phase A tiles (128 rows x 128B, XOR-swizzled): 64KB
#define QHI_OFF 0
#define QLO_OFF 16384
#define KHI_OFF 32768
#define KLO_OFF 49152
// phase B (overlays phase A, time-disjoint):
//   V tiles [128 j][40 bf16] pitch 80B (32 d per chunk), hi+lo, double buffered
#define VPITCH   80
#define VLO_REL  10240           // 128*80
#define VBUF     20480           // hi+lo per buffer
// partial-O exchange region (also reused for softmax max/g exchange)
#define P_OFF    40960
#define PPITCH   136             // 32 d * 4B + 8B pad (conflict-free rows)
#define MAXS_OFF P_OFF           // [128][2] floats   (softmax max exchange)
#define GS_OFF   (P_OFF + 1024)  // [128][2][8] floats (softmax group sums)
#define DYN_BYTES 65536

// ---------------- host-side Cantor table (keys sorted by (dmin, idx)) ----------------
struct CTab { int idx[129]; };
static CTab g_tab;

static bool build_tables() {
    std::vector<std::vector<long long>> idxd;
    auto to_idx = [](const std::vector<double>& p) {
        std::vector<long long> v;
        for (double x : p) v.push_back((long long)(x * 4095.0));
        std::sort(v.begin(), v.end());
        v.erase(std::unique(v.begin(), v.end()), v.end());
        return v;
    };
    std::vector<double> prev = {0.0, 1.0};
    idxd.push_back(to_idx(prev));
    for (int d = 1; d < NDEP; ++d) {
        std::vector<double> nw;
        for (size_t i = 0; i + 1 < prev.size(); ++i) {
            double left = prev[i], right = prev[i + 1];
            double third = (right - left) / 3.0;
            nw.push_back(left);
            nw.push_back(left + third);
        }
        nw.push_back(prev.back());
        prev.swap(nw);
        idxd.push_back(to_idx(prev));
    }
    const std::vector<long long>& uni = idxd[NDEP - 1];   // 129 keys (nested union)
    int nu = (int)uni.size();
    std::vector<std::pair<int, long long>> keys;
    for (int j = 0; j < nu; ++j) {
        int dm = NDEP - 1;
        for (int d = 0; d < NDEP; ++d)
            if (std::binary_search(idxd[d].begin(), idxd[d].end(), uni[j])) { dm = d; break; }
        keys.push_back({dm, uni[j]});
    }
    std::sort(keys.begin(), keys.end());
    for (int j = 0; j < nu && j < 129; ++j) g_tab.idx[j] = (int)keys[j].second;
    return true;
}
static bool g_built = build_tables();
// sorted-slot depth groups: bnd = {0,2,3,5,9,17,33,65,129}

// ---------------- helpers ----------------
__device__ __forceinline__ uint32_t s2u(const void* p) {
    uint32_t a;
    asm("{ .reg .u64 t; cvta.to.shared.u64 t, %1; cvt.u32.u64 %0, t; }" : "=r"(a) : "l"(p));
    return a;
}

#define LDSM4(r0, r1, r2, r3, addr) \
    asm volatile("ldmatrix.sync.aligned.m8n8.x4.shared.b16 {%0,%1,%2,%3}, [%4];" \
                 : "=r"(r0), "=r"(r1), "=r"(r2), "=r"(r3) : "r"(addr))

#define LDSM4T(r0, r1, r2, r3, addr) \
    asm volatile("ldmatrix.sync.aligned.m8n8.x4.trans.shared.b16 {%0,%1,%2,%3}, [%4];" \
                 : "=r"(r0), "=r"(r1), "=r"(r2), "=r"(r3) : "r"(addr))

#define MMA(d, a0, a1, a2, a3, b0, b1) \
    asm volatile("mma.sync.aligned.m16n8k16.row.col.f32.bf16.bf16.f32 " \
                 "{%0,%1,%2,%3}, {%4,%5,%6,%7}, {%8,%9}, {%0,%1,%2,%3};" \
                 : "+f"((d)[0]), "+f"((d)[1]), "+f"((d)[2]), "+f"((d)[3]) \
                 : "r"(a0), "r"(a1), "r"(a2), "r"(a3), "r"(b0), "r"(b1))

// split x -> hi (round-to-nearest bf16) + lo (rounded bf16 of exact remainder); pack 2
__device__ __forceinline__ void split2(float c0, float c1, uint32_t& hi, uint32_t& lo) {
    asm("cvt.rn.bf16x2.f32 %0, %1, %2;" : "=r"(hi) : "f"(c1), "f"(c0));
    float h0 = __uint_as_float(hi << 16);
    float h1 = __uint_as_float(hi & 0xFFFF0000u);
    float l0 = c0 - h0;   // exact in fp32
    float l1 = c1 - h1;
    asm("cvt.rn.bf16x2.f32 %0, %1, %2;" : "=r"(lo) : "f"(l1), "f"(l0));
}
__device__ __forceinline__ void split_store4(char* hiB, char* loB, uint32_t off, float4 v) {
    uint32_t h01, l01, h23, l23;
    split2(v.x, v.y, h01, l01);
    split2(v.z, v.w, h23, l23);
    *(uint2*)(hiB + off) = make_uint2(h01, h23);
    *(uint2*)(loB + off) = make_uint2(l01, l23);
}

// depth-group accumulation (ntg literal after unroll -> all indices static)
__device__ __forceinline__ void gacc(int nt, float* g, float e0, float e1, int t) {
    if (nt == 0) {
        g[0] += (t == 0) ? (e0 + e1) : 0.f;
        g[1] += (t == 1) ? e0 : 0.f;
        g[2] += (t == 1) ? e1 : ((t == 2) ? e0 : 0.f);
        g[3] += (t == 2) ? e1 : ((t == 3) ? (e0 + e1) : 0.f);
    } else if (nt == 1) {
        g[3] += (t == 0) ? e0 : 0.f;
        g[4] += (t == 0) ? e1 : (e0 + e1);
    } else if (nt == 2) {
        g[4] += (t == 0) ? e0 : 0.f;
        g[5] += (t == 0) ? e1 : (e0 + e1);
    } else if (nt == 3) {
        g[5] += e0 + e1;
    } else if (nt == 4) {
        g[5] += (t == 0) ? e0 : 0.f;
        g[6] += (t == 0) ? e1 : (e0 + e1);
    } else if (nt <= 7) {
        g[6] += e0 + e1;
    } else if (nt == 8) {
        g[6] += (t == 0) ? e0 : 0.f;
        g[7] += (t == 0) ? e1 : (e0 + e1);
    } else {
        g[7] += e0 + e1;
    }
}
__device__ __forceinline__ float2 samul(int nt, const float* sa, int t) {
    float m0, m1;
    if (nt == 0) {
        m0 = (t == 0) ? sa[0] : (t == 1) ? sa[1] : (t == 2) ? sa[2] : sa[3];
        m1 = (t == 0) ? sa[0] : (t == 1) ? sa[2] : sa[3];
    } else if (nt == 1) { m0 = (t == 0) ? sa[3] : sa[4]; m1 = sa[4]; }
    else if (nt == 2)   { m0 = (t == 0) ? sa[4] : sa[5]; m1 = sa[5]; }
    else if (nt == 3)   { m0 = sa[5]; m1 = sa[5]; }
    else if (nt == 4)   { m0 = (t == 0) ? sa[5] : sa[6]; m1 = sa[6]; }
    else if (nt <= 7)   { m0 = sa[6]; m1 = sa[6]; }
    else if (nt == 8)   { m0 = (t == 0) ? sa[6] : sa[7]; m1 = sa[7]; }
    else                { m0 = sa[7]; m1 = sa[7]; }
    return make_float2(m0, m1);
}

// ---------------- kernel ----------------
__global__ __launch_bounds__(NTH, 2)
void ufa9_kernel(const float* __restrict__ Q, const float* __restrict__ K,
                 const float* __restrict__ V, const float* __restrict__ SW,
                 const float* __restrict__ ST, float* __restrict__ O, CTab tab)
{
    extern __shared__ char AB[];
    const uint32_t ab = s2u(AB);

    __shared__ int   si[129];
    __shared__ float wv[NDEP];
    __shared__ float s128s[128];
    __shared__ float c128s[128];

    const int tid  = threadIdx.x;
    const int w    = tid >> 5;
    const int lane = tid & 31;
    const int b    = blockIdx.y;
    const int q0   = blockIdx.x * QT;
    const float inv_scale = 0.04419417382415922f;  // 1/sqrt(512)

    const int p  = w >> 1;      // warp pair: rows 32p..32p+31
    const int sd = w & 1;       // side: j/k columns 64*sd..64*sd+63
    const int lr = lane & 15;
    const int lc = lane >> 4;
    const int t4 = lane & 3;
    const int rq = lane >> 2;

    for (int i = tid; i < 129; i += NTH) si[i] = tab.idx[i];
    if (tid == 0) {
        float tmp = ST[0];
        float vvv[NDEP];
        float m = -1e30f;
        #pragma unroll
        for (int d = 0; d < NDEP; ++d) { vvv[d] = SW[d] / tmp; m = fmaxf(m, vvv[d]); }
        float s = 0.f;
        #pragma unroll
        for (int d = 0; d < NDEP; ++d) { vvv[d] = __expf(vvv[d] - m); s += vvv[d]; }
        #pragma unroll
        for (int d = 0; d < NDEP; ++d) wv[d] = vvv[d] / s;
    }
    __syncthreads();

    // ---- raw score column j = 128 ----
    {
        int q = tid >> 1, h = tid & 1;
        const float4* qr = (const float4*)(Q + ((size_t)b * S_ + q0 + q) * D_ + h * 256);
        const float4* kr = (const float4*)(K + ((size_t)b * S_ + si[128]) * D_ + h * 256);
        float s = 0.f;
        #pragma unroll 8
        for (int i = 0; i < 64; ++i) {
            float4 a = qr[i], c = kr[i];
            s = fmaf(a.x, c.x, s); s = fmaf(a.y, c.y, s);
            s = fmaf(a.z, c.z, s); s = fmaf(a.w, c.w, s);
        }
        s += __shfl_xor_sync(0xffffffffu, s, 1);
        if (h == 0) s128s[q] = s;   // RAW (scaled later in softmax)
    }

    // ================= phase A: S = Q.K^T (raw), split-bf16 mma =================
    // warp computes rows [32p,32p+32) x cols [64sd, 64sd+64): acc[mt][nt][4]
    float acc[2][8][4];
    #pragma unroll
    for (int mt = 0; mt < 2; ++mt)
        #pragma unroll
        for (int nt = 0; nt < 8; ++nt)
            #pragma unroll
            for (int i = 0; i < 4; ++i)
                acc[mt][nt][i] = 0.f;

    const int frow = tid >> 1;
    const int fkh  = (tid & 1) * 32;

    #pragma unroll 1
    for (int ck = 0; ck < 8; ++ck) {
        // fill Q/K split tiles for this 64-dim chunk (128B rows, XOR-swizzled 16B chunks)
        {
            const float4* Qr = (const float4*)(Q + ((size_t)b * S_ + q0 + frow) * D_ + ck * 64 + fkh);
            const float4* Kr = (const float4*)(K + ((size_t)b * S_ + si[frow]) * D_ + ck * 64 + fkh);
            #pragma unroll
            for (int i = 0; i < 8; ++i) {
                const int k = fkh + i * 4;
                const uint32_t off = frow * 128 + (((k >> 3) ^ (frow & 7)) * 16) + (k & 7) * 2;
                split_store4(AB + QHI_OFF, AB + QLO_OFF, off, Qr[i]);
                split_store4(AB + KHI_OFF, AB + KLO_OFF, off, Kr[i]);
            }
        }
        __syncthreads();
        #pragma unroll
        for (int kk = 0; kk < 4; ++kk) {
            const uint32_t coff = (uint32_t)(((2 * kk + lc) ^ (lr & 7)) * 16);
            uint32_t ah[2][4], al[2][4];
            #pragma unroll
            for (int mt = 0; mt < 2; ++mt) {
                const uint32_t arow = (uint32_t)((p * 32 + mt * 16 + lr) * 128);
                LDSM4(ah[mt][0], ah[mt][1], ah[mt][2], ah[mt][3], ab + QHI_OFF + arow + coff);
                LDSM4(al[mt][0], al[mt][1], al[mt][2], al[mt][3], ab + QLO_OFF + arow + coff);
            }
            #pragma unroll
            for (int ng = 0; ng < 4; ++ng) {
                const uint32_t boff = (uint32_t)((sd * 64 + ng * 16 + lr) * 128) + coff;
                uint32_t bh0, bh1, bh2, bh3, bl0, bl1, bl2, bl3;
                LDSM4(bh0, bh1, bh2, bh3, ab + KHI_OFF + boff);
                LDSM4(bl0, bl1, bl2, bl3, ab + KLO_OFF + boff);
                #pragma unroll
                for (int mt = 0; mt < 2; ++mt) {
                    MMA(acc[mt][2 * ng],     ah[mt][0], ah[mt][1], ah[mt][2], ah[mt][3], bh0, bh2);
                    MMA(acc[mt][2 * ng],     al[mt][0], al[mt][1], al[mt][2], al[mt][3], bh0, bh2);
                    MMA(acc[mt][2 * ng],     ah[mt][0], ah[mt][1], ah[mt][2], ah[mt][3], bl0, bl2);
                    MMA(acc[mt][2 * ng + 1], ah[mt][0], ah[mt][1], ah[mt][2], ah[mt][3], bh1, bh3);
                    MMA(acc[mt][2 * ng + 1], al[mt][0], al[mt][1], al[mt][2], al[mt][3], bh1, bh3);
                    MMA(acc[mt][2 * ng + 1], ah[mt][0], ah[mt][1], ah[mt][2], ah[mt][3], bl1, bl3);
                }
            }
        }
        __syncthreads();
    }
    // tiles dead from here.

    // ---- phase B chunk-0 V fill issued early (overlaps softmax) ----
    auto fillV = [&](int t, int buf) {
        const int fj = tid >> 1;
        const int fh = tid & 1;
        char* vb = AB + buf * VBUF;
        const float4* Vr = (const float4*)(V + ((size_t)b * S_ + si[fj]) * D_ + t * 32 + fh * 16);
        #pragma unroll
        for (int i = 0; i < 4; ++i) {
            float4 v = Vr[i];
            uint32_t h01, l01, h23, l23;
            split2(v.x, v.y, h01, l01);
            split2(v.z, v.w, h23, l23);
            const uint32_t off = fj * VPITCH + fh * 32 + i * 8;
            *(uint2*)(vb + off)           = make_uint2(h01, h23);
            *(uint2*)(vb + VLO_REL + off) = make_uint2(l01, l23);
        }
    };
    fillV(0, 0);

    // ================= softmax (cross-warp pair exchange) =================
    // lane rows: rs=0..3 -> p*32 + (rs>>1)*16 + (rs&1)*8 + rq ; cols j = 64sd + nt*8 + 2t4+{0,1}
    uint32_t chi[2][4][4], clo[2][4][4];
    {
        float mx[4];
        #pragma unroll
        for (int rs = 0; rs < 4; ++rs)
            mx[rs] = s128s[p * 32 + (rs >> 1) * 16 + (rs & 1) * 8 + rq];
        #pragma unroll
        for (int mt = 0; mt < 2; ++mt)
            #pragma unroll
            for (int nt = 0; nt < 8; ++nt) {
                mx[2 * mt]     = fmaxf(mx[2 * mt],     fmaxf(acc[mt][nt][0], acc[mt][nt][1]));
                mx[2 * mt + 1] = fmaxf(mx[2 * mt + 1], fmaxf(acc[mt][nt][2], acc[mt][nt][3]));
            }
        #pragma unroll
        for (int rs = 0; rs < 4; ++rs) {
            mx[rs] = fmaxf(mx[rs], __shfl_xor_sync(0xffffffffu, mx[rs], 1));
            mx[rs] = fmaxf(mx[rs], __shfl_xor_sync(0xffffffffu, mx[rs], 2));
        }
        if (t4 == 0) {
            #pragma unroll
            for (int rs = 0; rs < 4; ++rs) {
                const int row = p * 32 + (rs >> 1) * 16 + (rs & 1) * 8 + rq;
                *(float*)(AB + MAXS_OFF + (row * 2 + sd) * 4) = mx[rs];
            }
        }
        __syncthreads();
        #pragma unroll
        for (int rs = 0; rs < 4; ++rs) {
            const int row = p * 32 + (rs >> 1) * 16 + (rs & 1) * 8 + rq;
            float m0 = *(float*)(AB + MAXS_OFF + (row * 2 + 0) * 4);
            float m1 = *(float*)(AB + MAXS_OFF + (row * 2 + 1) * 4);
            mx[rs] = fmaxf(m0, m1);
        }

        float g[4][NDEP];
        #pragma unroll
        for (int rs = 0; rs < 4; ++rs)
            #pragma unroll
            for (int d = 0; d < NDEP; ++d) g[rs][d] = 0.f;
        #pragma unroll
        for (int nt = 0; nt < 8; ++nt) {
            const int ntg = sd * 8 + nt;
            #pragma unroll
            for (int mt = 0; mt < 2; ++mt) {
                float e0 = __expf((acc[mt][nt][0] - mx[2 * mt]) * inv_scale);
                float e1 = __expf((acc[mt][nt][1] - mx[2 * mt]) * inv_scale);
                float e2 = __expf((acc[mt][nt][2] - mx[2 * mt + 1]) * inv_scale);
                float e3 = __expf((acc[mt][nt][3] - mx[2 * mt + 1]) * inv_scale);
                acc[mt][nt][0] = e0; acc[mt][nt][1] = e1;
                acc[mt][nt][2] = e2; acc[mt][nt][3] = e3;
                gacc(ntg, g[2 * mt], e0, e1, t4);
                gacc(ntg, g[2 * mt + 1], e2, e3, t4);
            }
        }
        #pragma unroll
        for (int rs = 0; rs < 4; ++rs)
            #pragma unroll
            for (int d = 0; d < NDEP; ++d) {
                g[rs][d] += __shfl_xor_sync(0xffffffffu, g[rs][d], 1);
                g[rs][d] += __shfl_xor_sync(0xffffffffu, g[rs][d], 2);
            }
        if (t4 == 0) {
            #pragma unroll
            for (int rs = 0; rs < 4; ++rs) {
                const int row = p * 32 + (rs >> 1) * 16 + (rs & 1) * 8 + rq;
                *(float4*)(AB + GS_OFF + row * 64 + sd * 32)      = make_float4(g[rs][0], g[rs][1], g[rs][2], g[rs][3]);
                *(float4*)(AB + GS_OFF + row * 64 + sd * 32 + 16) = make_float4(g[rs][4], g[rs][5], g[rs][6], g[rs][7]);
            }
        }
        __syncthreads();

        float sa[4][NDEP];
        #pragma unroll
        for (int rs = 0; rs < 4; ++rs) {
            const int row = p * 32 + (rs >> 1) * 16 + (rs & 1) * 8 + rq;
            float4 a0 = *(float4*)(AB + GS_OFF + row * 64);
            float4 a1 = *(float4*)(AB + GS_OFF + row * 64 + 16);
            float4 b0 = *(float4*)(AB + GS_OFF + row * 64 + 32);
            float4 b1 = *(float4*)(AB + GS_OFF + row * 64 + 48);
            float gt[NDEP] = {a0.x + b0.x, a0.y + b0.y, a0.z + b0.z, a0.w + b0.w,
                              a1.x + b1.x, a1.y + b1.y, a1.z + b1.z, a1.w + b1.w};
            const float e128 = __expf((s128s[row] - mx[rs]) * inv_scale);
            gt[7] += e128;
            float Z = 0.f, zr[NDEP];
            #pragma unroll
            for (int d = 0; d < NDEP; ++d) { Z += gt[d]; zr[d] = __fdividef(wv[d], Z); }
            float ss = 0.f;
            #pragma unroll
            for (int d = NDEP - 1; d >= 0; --d) { ss += zr[d]; sa[rs][d] = ss; }
            if (sd == 0 && t4 == 0) c128s[row] = e128 * sa[rs][7];
        }

        // coefficients -> mma A-fragment registers (acc layout == A-frag layout)
        #pragma unroll
        for (int mt = 0; mt < 2; ++mt)
            #pragma unroll
            for (int nt = 0; nt < 8; ++nt) {
                const int ntg = sd * 8 + nt;
                float2 mu0 = samul(ntg, sa[2 * mt], t4);
                float2 mu1 = samul(ntg, sa[2 * mt + 1], t4);
                const int kk = nt >> 1;
                const int o  = (nt & 1) * 2;
                split2(acc[mt][nt][0] * mu0.x, acc[mt][nt][1] * mu0.y, chi[mt][kk][o],     clo[mt][kk][o]);
                split2(acc[mt][nt][2] * mu1.x, acc[mt][nt][3] * mu1.y, chi[mt][kk][o + 1], clo[mt][kk][o + 1]);
            }
    }
    __syncthreads();   // fillV(0) visible; exchange done; c128s ready

    // ================= phase B: O = C . V  (16 d-chunks of 32, double-buffered V,
    //                    pair-partial combine through smem) =================
    const int si128 = si[128];
    #pragma unroll 1
    for (int t = 0; t < 16; ++t) {
        const int buf = t & 1;
        if (t < 15) fillV(t + 1, buf ^ 1);

        float oa[2][4][4];
        #pragma unroll
        for (int mt = 0; mt < 2; ++mt)
            #pragma unroll
            for (int nt = 0; nt < 4; ++nt)
                #pragma unroll
                for (int i = 0; i < 4; ++i)
                    oa[mt][nt][i] = 0.f;

        #pragma unroll
        for (int kk = 0; kk < 4; ++kk) {
            #pragma unroll
            for (int ng = 0; ng < 2; ++ng) {
                const uint32_t a0 = ab + buf * VBUF
                    + (uint32_t)((sd * 64 + kk * 16 + lr) * VPITCH) + lc * 16 + ng * 32;
                uint32_t vh0, vh1, vh2, vh3, vl0, vl1, vl2, vl3;
                LDSM4T(vh0, vh1, vh2, vh3, a0);
                LDSM4T(vl0, vl1, vl2, vl3, a0 + VLO_REL);
                #pragma unroll
                for (int mt = 0; mt < 2; ++mt) {
                    MMA(oa[mt][2 * ng],     chi[mt][kk][0], chi[mt][kk][1], chi[mt][kk][2], chi[mt][kk][3], vh0, vh1);
                    MMA(oa[mt][2 * ng],     clo[mt][kk][0], clo[mt][kk][1], clo[mt][kk][2], clo[mt][kk][3], vh0, vh1);
                    MMA(oa[mt][2 * ng],     chi[mt][kk][0], chi[mt][kk][1], chi[mt][kk][2], chi[mt][kk][3], vl0, vl1);
                    MMA(oa[mt][2 * ng + 1], chi[mt][kk][0], chi[mt][kk][1], chi[mt][kk][2], chi[mt][kk][3], vh2, vh3);
                    MMA(oa[mt][2 * ng + 1], clo[mt][kk][0], clo[mt][kk][1], clo[mt][kk][2], clo[mt][kk][3], vh2, vh3);
                    MMA(oa[mt][2 * ng + 1], chi[mt][kk][0], chi[mt][kk][1], chi[mt][kk][2], chi[mt][kk][3], vl2, vl3);
                }
            }
        }

        // ship partner's half (mt = 1-sd) through smem
        {
            const int hp = 1 - sd;
            const int r0 = p * 32 + hp * 16 + rq;
            #pragma unroll
            for (int nt = 0; nt < 4; ++nt) {
                const uint32_t c4 = (uint32_t)((nt * 8 + 2 * t4) * 4);
                *(float2*)(AB + P_OFF + r0 * PPITCH + c4)       = make_float2(oa[hp][nt][0], oa[hp][nt][1]);
                *(float2*)(AB + P_OFF + (r0 + 8) * PPITCH + c4) = make_float2(oa[hp][nt][2], oa[hp][nt][3]);
            }
        }
        __syncthreads();

        // combine own half (mt = sd) with partner's partial; epilogue; store O
        {
            const int r0 = p * 32 + sd * 16 + rq;
            const float cA = c128s[r0], cB = c128s[r0 + 8];
            const float* v128 = V + ((size_t)b * S_ + si128) * D_ + t * 32;
            float* OA = O + ((size_t)b * S_ + q0 + r0) * D_ + t * 32;
            float* OB = OA + 8 * D_;
            #pragma unroll
            for (int nt = 0; nt < 4; ++nt) {
                const int nc = nt * 8 + 2 * t4;
                const uint32_t c4 = (uint32_t)(nc * 4);
                float2 pa = *(float2*)(AB + P_OFF + r0 * PPITCH + c4);
                float2 pb = *(float2*)(AB + P_OFF + (r0 + 8) * PPITCH + c4);
                float2 vv = *(const float2*)(v128 + nc);
                *(float2*)(OA + nc) = make_float2(oa[sd][nt][0] + pa.x + cA * vv.x,
                                                  oa[sd][nt][1] + pa.y + cA * vv.y);
                *(float2*)(OB + nc) = make_float2(oa[sd][nt][2] + pb.x + cB * vv.x,
                                                  oa[sd][nt][3] + pb.y + cB * vv.y);
            }
        }
        __syncthreads();
    }
}

// ---------------- launch ----------------
extern "C" void kernel_launch(void* const* d_in, const int* in_sizes, int n_in,
                              void* d_out, int out_size)
{
    const float* Q  = (const float*)d_in[0];
    const float* K  = (const float*)d_in[1];
    const float* V  = (const float*)d_in[2];
    // d_in[3] = t (unused by the reference)
    const float* SW = (const float*)d_in[4];
    const float* ST = (const float*)d_in[5];
    float* O = (float*)d_out;

    cudaFuncSetAttribute(ufa9_kernel, cudaFuncAttributeMaxDynamicSharedMemorySize, DYN_BYTES);

    dim3 grid(S_ / QT, B_);
    ufa9_kernel<<<grid, NTH, DYN_BYTES>>>(Q, K, V, SW, ST, O, g_tab);
}

// round 11
// speedup vs baseline: 1.1532x; 1.1532x over previous
#include <cuda_runtime.h>
#include <cuda_bf16.h>
#include <cuda_fp16.h>
#include <cstdint>
#include <vector>
#include <algorithm>

// ---------------- problem constants ----------------
#define B_    8
#define S_    4096
#define D_    512
#define QT    128
#define NTH   256
#define NDEP  8

// smem byte offsets (dynamic smem base AB)
// phase A tiles (128 rows x 128B, XOR-swizzled): 64KB
#define QHI_OFF 0
#define QLO_OFF 16384
#define KHI_OFF 32768
#define KLO_OFF 49152
// phase B: V tiles [128 j][72 fp16] pitch 144B (single fp16!), double buffered (overlays A)
#define VPITCH   144
#define VBUF     18432           // 128*144 per buffer
#define DYN_BYTES 65536

// ---------------- host-side Cantor table (keys sorted by (dmin, idx)) ----------------
struct CTab { int idx[129]; };
static CTab g_tab;

static bool build_tables() {
    std::vector<std::vector<long long>> idxd;
    auto to_idx = [](const std::vector<double>& p) {
        std::vector<long long> v;
        for (double x : p) v.push_back((long long)(x * 4095.0));
        std::sort(v.begin(), v.end());
        v.erase(std::unique(v.begin(), v.end()), v.end());
        return v;
    };
    std::vector<double> prev = {0.0, 1.0};
    idxd.push_back(to_idx(prev));
    for (int d = 1; d < NDEP; ++d) {
        std::vector<double> nw;
        for (size_t i = 0; i + 1 < prev.size(); ++i) {
            double left = prev[i], right = prev[i + 1];
            double third = (right - left) / 3.0;
            nw.push_back(left);
            nw.push_back(left + third);
        }
        nw.push_back(prev.back());
        prev.swap(nw);
        idxd.push_back(to_idx(prev));
    }
    const std::vector<long long>& uni = idxd[NDEP - 1];   // 129 keys (nested union)
    int nu = (int)uni.size();
    std::vector<std::pair<int, long long>> keys;
    for (int j = 0; j < nu; ++j) {
        int dm = NDEP - 1;
        for (int d = 0; d < NDEP; ++d)
            if (std::binary_search(idxd[d].begin(), idxd[d].end(), uni[j])) { dm = d; break; }
        keys.push_back({dm, uni[j]});
    }
    std::sort(keys.begin(), keys.end());
    for (int j = 0; j < nu && j < 129; ++j) g_tab.idx[j] = (int)keys[j].second;
    return true;
}
static bool g_built = build_tables();
// sorted-slot depth groups: bnd = {0,2,3,5,9,17,33,65,129}

// ---------------- helpers ----------------
__device__ __forceinline__ uint32_t s2u(const void* p) {
    uint32_t a;
    asm("{ .reg .u64 t; cvta.to.shared.u64 t, %1; cvt.u32.u64 %0, t; }" : "=r"(a) : "l"(p));
    return a;
}

#define LDSM4(r0, r1, r2, r3, addr) \
    asm volatile("ldmatrix.sync.aligned.m8n8.x4.shared.b16 {%0,%1,%2,%3}, [%4];" \
                 : "=r"(r0), "=r"(r1), "=r"(r2), "=r"(r3) : "r"(addr))

#define LDSM4T(r0, r1, r2, r3, addr) \
    asm volatile("ldmatrix.sync.aligned.m8n8.x4.trans.shared.b16 {%0,%1,%2,%3}, [%4];" \
                 : "=r"(r0), "=r"(r1), "=r"(r2), "=r"(r3) : "r"(addr))

#define MMA(d, a0, a1, a2, a3, b0, b1) \
    asm volatile("mma.sync.aligned.m16n8k16.row.col.f32.bf16.bf16.f32 " \
                 "{%0,%1,%2,%3}, {%4,%5,%6,%7}, {%8,%9}, {%0,%1,%2,%3};" \
                 : "+f"((d)[0]), "+f"((d)[1]), "+f"((d)[2]), "+f"((d)[3]) \
                 : "r"(a0), "r"(a1), "r"(a2), "r"(a3), "r"(b0), "r"(b1))

#define MMAH(d, a0, a1, a2, a3, b0, b1) \
    asm volatile("mma.sync.aligned.m16n8k16.row.col.f32.f16.f16.f32 " \
                 "{%0,%1,%2,%3}, {%4,%5,%6,%7}, {%8,%9}, {%0,%1,%2,%3};" \
                 : "+f"((d)[0]), "+f"((d)[1]), "+f"((d)[2]), "+f"((d)[3]) \
                 : "r"(a0), "r"(a1), "r"(a2), "r"(a3), "r"(b0), "r"(b1))

// split x -> hi (round-to-nearest bf16) + lo (rounded bf16 of exact remainder); pack 2
__device__ __forceinline__ void split2(float c0, float c1, uint32_t& hi, uint32_t& lo) {
    asm("cvt.rn.bf16x2.f32 %0, %1, %2;" : "=r"(hi) : "f"(c1), "f"(c0));
    float h0 = __uint_as_float(hi << 16);
    float h1 = __uint_as_float(hi & 0xFFFF0000u);
    float l0 = c0 - h0;   // exact in fp32
    float l1 = c1 - h1;
    asm("cvt.rn.bf16x2.f32 %0, %1, %2;" : "=r"(lo) : "f"(l1), "f"(l0));
}
__device__ __forceinline__ void split_store4(char* hiB, char* loB, uint32_t off, float4 v) {
    uint32_t h01, l01, h23, l23;
    split2(v.x, v.y, h01, l01);
    split2(v.z, v.w, h23, l23);
    *(uint2*)(hiB + off) = make_uint2(h01, h23);
    *(uint2*)(loB + off) = make_uint2(l01, l23);
}
// fp16 split: hi = rn-f16(x), lo = rn-f16(x - hi)
__device__ __forceinline__ void split2h(float c0, float c1, uint32_t& hi, uint32_t& lo) {
    __half2 h = __floats2half2_rn(c0, c1);
    hi = *(uint32_t*)&h;
    float2 hf = __half22float2(h);
    __half2 l = __floats2half2_rn(c0 - hf.x, c1 - hf.y);
    lo = *(uint32_t*)&l;
}
__device__ __forceinline__ uint32_t pack_h2(float c0, float c1) {
    __half2 h = __floats2half2_rn(c0, c1);
    return *(uint32_t*)&h;
}

// depth-group accumulation (nt literal after unroll -> all indices static)
__device__ __forceinline__ void gacc(int nt, float* g, float e0, float e1, int t) {
    if (nt == 0) {
        g[0] += (t == 0) ? (e0 + e1) : 0.f;
        g[1] += (t == 1) ? e0 : 0.f;
        g[2] += (t == 1) ? e1 : ((t == 2) ? e0 : 0.f);
        g[3] += (t == 2) ? e1 : ((t == 3) ? (e0 + e1) : 0.f);
    } else if (nt == 1) {
        g[3] += (t == 0) ? e0 : 0.f;
        g[4] += (t == 0) ? e1 : (e0 + e1);
    } else if (nt == 2) {
        g[4] += (t == 0) ? e0 : 0.f;
        g[5] += (t == 0) ? e1 : (e0 + e1);
    } else if (nt == 3) {
        g[5] += e0 + e1;
    } else if (nt == 4) {
        g[5] += (t == 0) ? e0 : 0.f;
        g[6] += (t == 0) ? e1 : (e0 + e1);
    } else if (nt <= 7) {
        g[6] += e0 + e1;
    } else if (nt == 8) {
        g[6] += (t == 0) ? e0 : 0.f;
        g[7] += (t == 0) ? e1 : (e0 + e1);
    } else {
        g[7] += e0 + e1;
    }
}
__device__ __forceinline__ float2 samul(int nt, const float* sa, int t) {
    float m0, m1;
    if (nt == 0) {
        m0 = (t == 0) ? sa[0] : (t == 1) ? sa[1] : (t == 2) ? sa[2] : sa[3];
        m1 = (t == 0) ? sa[0] : (t == 1) ? sa[2] : sa[3];
    } else if (nt == 1) { m0 = (t == 0) ? sa[3] : sa[4]; m1 = sa[4]; }
    else if (nt == 2)   { m0 = (t == 0) ? sa[4] : sa[5]; m1 = sa[5]; }
    else if (nt == 3)   { m0 = sa[5]; m1 = sa[5]; }
    else if (nt == 4)   { m0 = (t == 0) ? sa[5] : sa[6]; m1 = sa[6]; }
    else if (nt <= 7)   { m0 = sa[6]; m1 = sa[6]; }
    else if (nt == 8)   { m0 = (t == 0) ? sa[6] : sa[7]; m1 = sa[7]; }
    else                { m0 = sa[7]; m1 = sa[7]; }
    return make_float2(m0, m1);
}

// ---------------- kernel ----------------
__global__ __launch_bounds__(NTH, 2)
void ufa10_kernel(const float* __restrict__ Q, const float* __restrict__ K,
                  const float* __restrict__ V, const float* __restrict__ SW,
                  const float* __restrict__ ST, float* __restrict__ O, CTab tab)
{
    extern __shared__ char AB[];
    const uint32_t ab = s2u(AB);

    __shared__ int   si[129];
    __shared__ float wv[NDEP];
    __shared__ float s128s[128];
    __shared__ float c128s[128];

    const int tid  = threadIdx.x;
    const int w    = tid >> 5;
    const int lane = tid & 31;
    const int b    = blockIdx.y;
    const int q0   = blockIdx.x * QT;
    const float inv_scale = 0.04419417382415922f;  // 1/sqrt(512)

    const int lr = lane & 15;   // ldmatrix row-within-16
    const int lc = lane >> 4;   // ldmatrix k-half
    const int t4 = lane & 3;
    const int rq = lane >> 2;   // fragment row 0..7

    for (int i = tid; i < 129; i += NTH) si[i] = tab.idx[i];
    if (tid == 0) {
        float tmp = ST[0];
        float vvv[NDEP];
        float m = -1e30f;
        #pragma unroll
        for (int d = 0; d < NDEP; ++d) { vvv[d] = SW[d] / tmp; m = fmaxf(m, vvv[d]); }
        float s = 0.f;
        #pragma unroll
        for (int d = 0; d < NDEP; ++d) { vvv[d] = __expf(vvv[d] - m); s += vvv[d]; }
        #pragma unroll
        for (int d = 0; d < NDEP; ++d) wv[d] = vvv[d] / s;
    }
    __syncthreads();

    // ---- raw score column j = 128 ----
    {
        int q = tid >> 1, h = tid & 1;
        const float4* qr = (const float4*)(Q + ((size_t)b * S_ + q0 + q) * D_ + h * 256);
        const float4* kr = (const float4*)(K + ((size_t)b * S_ + si[128]) * D_ + h * 256);
        float s = 0.f;
        #pragma unroll 8
        for (int i = 0; i < 64; ++i) {
            float4 a = qr[i], c = kr[i];
            s = fmaf(a.x, c.x, s); s = fmaf(a.y, c.y, s);
            s = fmaf(a.z, c.z, s); s = fmaf(a.w, c.w, s);
        }
        s += __shfl_xor_sync(0xffffffffu, s, 1);
        if (h == 0) s128s[q] = s;   // RAW (scaled later in softmax)
    }

    // ================= phase A: S = Q.K^T (raw), split-bf16 mma =================
    float acc[16][4];
    #pragma unroll
    for (int nt = 0; nt < 16; ++nt)
        #pragma unroll
        for (int i = 0; i < 4; ++i)
            acc[nt][i] = 0.f;

    const int frow = tid >> 1;
    const int fkh  = (tid & 1) * 32;

    #pragma unroll 1
    for (int ck = 0; ck < 8; ++ck) {
        // fill Q/K split tiles for this 64-dim chunk (128B rows, XOR-swizzled 16B chunks)
        {
            const float4* Qr = (const float4*)(Q + ((size_t)b * S_ + q0 + frow) * D_ + ck * 64 + fkh);
            const float4* Kr = (const float4*)(K + ((size_t)b * S_ + si[frow]) * D_ + ck * 64 + fkh);
            #pragma unroll
            for (int i = 0; i < 8; ++i) {
                const int k = fkh + i * 4;
                const uint32_t off = frow * 128 + (((k >> 3) ^ (frow & 7)) * 16) + (k & 7) * 2;
                split_store4(AB + QHI_OFF, AB + QLO_OFF, off, Qr[i]);
                split_store4(AB + KHI_OFF, AB + KLO_OFF, off, Kr[i]);
            }
        }
        __syncthreads();
        const uint32_t arow = (w * 16 + lr) * 128;
        #pragma unroll
        for (int kk = 0; kk < 4; ++kk) {
            const uint32_t coff = (uint32_t)(((2 * kk + lc) ^ (lr & 7)) * 16);
            uint32_t ah0, ah1, ah2, ah3, al0, al1, al2, al3;
            LDSM4(ah0, ah1, ah2, ah3, ab + QHI_OFF + arow + coff);
            LDSM4(al0, al1, al2, al3, ab + QLO_OFF + arow + coff);
            #pragma unroll
            for (int np = 0; np < 8; ++np) {
                const uint32_t boff = (np * 16 + lr) * 128 + coff;
                uint32_t bh0, bh1, bh2, bh3, bl0, bl1, bl2, bl3;
                LDSM4(bh0, bh1, bh2, bh3, ab + KHI_OFF + boff);
                LDSM4(bl0, bl1, bl2, bl3, ab + KLO_OFF + boff);
                MMA(acc[2 * np],     ah0, ah1, ah2, ah3, bh0, bh2);
                MMA(acc[2 * np],     al0, al1, al2, al3, bh0, bh2);
                MMA(acc[2 * np],     ah0, ah1, ah2, ah3, bl0, bl2);
                MMA(acc[2 * np + 1], ah0, ah1, ah2, ah3, bh1, bh3);
                MMA(acc[2 * np + 1], al0, al1, al2, al3, bh1, bh3);
                MMA(acc[2 * np + 1], ah0, ah1, ah2, ah3, bl1, bl3);
            }
        }
        __syncthreads();
    }

    // ================= softmax in registers -> C fragments (fp16 hi/lo) in registers =================
    // lane holds rows (w*16 + rq) and (+8); cols j = nt*8 + 2*t4 + {0,1}
    uint32_t chi[8][4], clo[8][4];
    {
        const int qa = w * 16 + rq;
        float mA = s128s[qa], mB = s128s[qa + 8];
        #pragma unroll
        for (int nt = 0; nt < 16; ++nt) {
            mA = fmaxf(mA, fmaxf(acc[nt][0], acc[nt][1]));
            mB = fmaxf(mB, fmaxf(acc[nt][2], acc[nt][3]));
        }
        mA = fmaxf(mA, __shfl_xor_sync(0xffffffffu, mA, 1));
        mA = fmaxf(mA, __shfl_xor_sync(0xffffffffu, mA, 2));
        mB = fmaxf(mB, __shfl_xor_sync(0xffffffffu, mB, 1));
        mB = fmaxf(mB, __shfl_xor_sync(0xffffffffu, mB, 2));

        float gA[NDEP], gB[NDEP];
        #pragma unroll
        for (int d = 0; d < NDEP; ++d) { gA[d] = 0.f; gB[d] = 0.f; }
        #pragma unroll
        for (int nt = 0; nt < 16; ++nt) {
            float e0 = __expf((acc[nt][0] - mA) * inv_scale);
            float e1 = __expf((acc[nt][1] - mA) * inv_scale);
            float e2 = __expf((acc[nt][2] - mB) * inv_scale);
            float e3 = __expf((acc[nt][3] - mB) * inv_scale);
            acc[nt][0] = e0; acc[nt][1] = e1; acc[nt][2] = e2; acc[nt][3] = e3;
            gacc(nt, gA, e0, e1, t4);
            gacc(nt, gB, e2, e3, t4);
        }
        // quad reduction FIRST...
        #pragma unroll
        for (int d = 0; d < NDEP; ++d) {
            gA[d] += __shfl_xor_sync(0xffffffffu, gA[d], 1);
            gA[d] += __shfl_xor_sync(0xffffffffu, gA[d], 2);
            gB[d] += __shfl_xor_sync(0xffffffffu, gB[d], 1);
            gB[d] += __shfl_xor_sync(0xffffffffu, gB[d], 2);
        }
        // ...THEN the (lane-uniform) j=128 term, added exactly once
        const float eA128 = __expf((s128s[qa] - mA) * inv_scale);
        const float eB128 = __expf((s128s[qa + 8] - mB) * inv_scale);
        gA[7] += eA128;
        gB[7] += eB128;

        float ZA = 0.f, ZB = 0.f, saA[NDEP], saB[NDEP];
        #pragma unroll
        for (int d = 0; d < NDEP; ++d) {
            ZA += gA[d]; saA[d] = __fdividef(wv[d], ZA);
            ZB += gB[d]; saB[d] = __fdividef(wv[d], ZB);
        }
        float sA = 0.f, sB = 0.f;
        #pragma unroll
        for (int d = NDEP - 1; d >= 0; --d) {
            sA += saA[d]; saA[d] = sA;
            sB += saB[d]; saB[d] = sB;
        }
        if (t4 == 0) {
            c128s[qa]     = eA128 * saA[7];
            c128s[qa + 8] = eB128 * saB[7];
        }
        // coefficients -> fp16 mma A-fragment registers (acc layout == A-frag layout)
        #pragma unroll
        for (int nt = 0; nt < 16; ++nt) {
            float2 muA = samul(nt, saA, t4);
            float2 muB = samul(nt, saB, t4);
            const int kk = nt >> 1;
            const int o  = (nt & 1) * 2;
            split2h(acc[nt][0] * muA.x, acc[nt][1] * muA.y, chi[kk][o],     clo[kk][o]);
            split2h(acc[nt][2] * muB.x, acc[nt][3] * muB.y, chi[kk][o + 1], clo[kk][o + 1]);
        }
    }

    // ================= phase B: O = C . V  (8 d-chunks of 64, double-buffered fp16 V) =================
    // V tiles stored row-major [j][d] (pitch 144B), single fp16, consumed via ldmatrix.trans.
    auto fillV = [&](int dc, int s) {
        const int fj = tid >> 1;            // key row 0..127
        const int fh = tid & 1;             // 32-dim half
        char* vb = AB + s * VBUF;
        const float4* Vr = (const float4*)(V + ((size_t)b * S_ + si[fj]) * D_ + dc * 64 + fh * 32);
        #pragma unroll
        for (int i = 0; i < 8; ++i) {
            float4 v = Vr[i];
            const uint32_t off = fj * VPITCH + fh * 64 + i * 8;
            *(uint2*)(vb + off) = make_uint2(pack_h2(v.x, v.y), pack_h2(v.z, v.w));
        }
    };

    const int si128 = si[128];
    fillV(0, 0);
    __syncthreads();

    #pragma unroll 1
    for (int dc = 0; dc < 8; ++dc) {
        const int s = dc & 1;
        if (dc < 7) fillV(dc + 1, s ^ 1);

        float oa[8][4];
        #pragma unroll
        for (int nt = 0; nt < 8; ++nt)
            #pragma unroll
            for (int i = 0; i < 4; ++i)
                oa[nt][i] = 0.f;

        const uint32_t vbase = ab + s * VBUF + (lane & 15) * VPITCH + (lane >> 4) * 16;
        #pragma unroll
        for (int kk = 0; kk < 8; ++kk) {
            #pragma unroll
            for (int ng = 0; ng < 4; ++ng) {
                const uint32_t a0 = vbase + kk * (16 * VPITCH) + ng * 32;
                uint32_t vh0, vh1, vh2, vh3;
                LDSM4T(vh0, vh1, vh2, vh3, a0);
                MMAH(oa[2 * ng],     chi[kk][0], chi[kk][1], chi[kk][2], chi[kk][3], vh0, vh1);
                MMAH(oa[2 * ng],     clo[kk][0], clo[kk][1], clo[kk][2], clo[kk][3], vh0, vh1);
                MMAH(oa[2 * ng + 1], chi[kk][0], chi[kk][1], chi[kk][2], chi[kk][3], vh2, vh3);
                MMAH(oa[2 * ng + 1], clo[kk][0], clo[kk][1], clo[kk][2], clo[kk][3], vh2, vh3);
            }
        }

        // epilogue: add key-128 term (fp32 exact), store O
        {
            const int qa = w * 16 + rq;
            const float cA = c128s[qa], cB = c128s[qa + 8];
            const float* v128 = V + ((size_t)b * S_ + si128) * D_ + dc * 64;
            float* OA = O + ((size_t)b * S_ + q0 + qa) * D_ + dc * 64;
            float* OB = OA + 8 * D_;
            #pragma unroll
            for (int nt = 0; nt < 8; ++nt) {
                const int nc = nt * 8 + 2 * t4;
                const float2 vv = *(const float2*)(v128 + nc);
                *(float2*)(OA + nc) = make_float2(oa[nt][0] + cA * vv.x, oa[nt][1] + cA * vv.y);
                *(float2*)(OB + nc) = make_float2(oa[nt][2] + cB * vv.x, oa[nt][3] + cB * vv.y);
            }
        }
        __syncthreads();
    }
}

// ---------------- launch ----------------
extern "C" void kernel_launch(void* const* d_in, const int* in_sizes, int n_in,
                              void* d_out, int out_size)
{
    const float* Q  = (const float*)d_in[0];
    const float* K  = (const float*)d_in[1];
    const float* V  = (const float*)d_in[2];
    // d_in[3] = t (unused by the reference)
    const float* SW = (const float*)d_in[4];
    const float* ST = (const float*)d_in[5];
    float* O = (float*)d_out;

    cudaFuncSetAttribute(ufa10_kernel, cudaFuncAttributeMaxDynamicSharedMemorySize, DYN_BYTES);

    dim3 grid(S_ / QT, B_);
    ufa10_kernel<<<grid, NTH, DYN_BYTES>>>(Q, K, V, SW, ST, O, g_tab);
}

// round 12
// speedup vs baseline: 1.3011x; 1.1282x over previous
#include <cuda_runtime.h>
#include <cuda_bf16.h>
#include <cuda_fp16.h>
#include <cstdint>
#include <vector>
#include <algorithm>

// ---------------- problem constants ----------------
#define B_    8
#define S_    4096
#define D_    512
#define QT    128
#define NTH   256
#define NDEP  8

// smem byte offsets (dynamic smem base AB)
// phase A: single-fp16 Q/K tiles (128 rows x 128B, XOR-swizzled), double buffered
//   buf s at s*32768: Q at +0, K at +16384
#define ABUF     32768
// phase B: V tiles [128 j][72 fp16] pitch 144B (single fp16), double buffered (overlays A)
#define VPITCH   144
#define VBUF     18432           // 128*144 per buffer
#define DYN_BYTES 65536

// ---------------- host-side Cantor table (keys sorted by (dmin, idx)) ----------------
struct CTab { int idx[129]; };
static CTab g_tab;

static bool build_tables() {
    std::vector<std::vector<long long>> idxd;
    auto to_idx = [](const std::vector<double>& p) {
        std::vector<long long> v;
        for (double x : p) v.push_back((long long)(x * 4095.0));
        std::sort(v.begin(), v.end());
        v.erase(std::unique(v.begin(), v.end()), v.end());
        return v;
    };
    std::vector<double> prev = {0.0, 1.0};
    idxd.push_back(to_idx(prev));
    for (int d = 1; d < NDEP; ++d) {
        std::vector<double> nw;
        for (size_t i = 0; i + 1 < prev.size(); ++i) {
            double left = prev[i], right = prev[i + 1];
            double third = (right - left) / 3.0;
            nw.push_back(left);
            nw.push_back(left + third);
        }
        nw.push_back(prev.back());
        prev.swap(nw);
        idxd.push_back(to_idx(prev));
    }
    const std::vector<long long>& uni = idxd[NDEP - 1];   // 129 keys (nested union)
    int nu = (int)uni.size();
    std::vector<std::pair<int, long long>> keys;
    for (int j = 0; j < nu; ++j) {
        int dm = NDEP - 1;
        for (int d = 0; d < NDEP; ++d)
            if (std::binary_search(idxd[d].begin(), idxd[d].end(), uni[j])) { dm = d; break; }
        keys.push_back({dm, uni[j]});
    }
    std::sort(keys.begin(), keys.end());
    for (int j = 0; j < nu && j < 129; ++j) g_tab.idx[j] = (int)keys[j].second;
    return true;
}
static bool g_built = build_tables();
// sorted-slot depth groups: bnd = {0,2,3,5,9,17,33,65,129}

// ---------------- helpers ----------------
__device__ __forceinline__ uint32_t s2u(const void* p) {
    uint32_t a;
    asm("{ .reg .u64 t; cvta.to.shared.u64 t, %1; cvt.u32.u64 %0, t; }" : "=r"(a) : "l"(p));
    return a;
}

#define LDSM4(r0, r1, r2, r3, addr) \
    asm volatile("ldmatrix.sync.aligned.m8n8.x4.shared.b16 {%0,%1,%2,%3}, [%4];" \
                 : "=r"(r0), "=r"(r1), "=r"(r2), "=r"(r3) : "r"(addr))

#define LDSM4T(r0, r1, r2, r3, addr) \
    asm volatile("ldmatrix.sync.aligned.m8n8.x4.trans.shared.b16 {%0,%1,%2,%3}, [%4];" \
                 : "=r"(r0), "=r"(r1), "=r"(r2), "=r"(r3) : "r"(addr))

#define MMAH(d, a0, a1, a2, a3, b0, b1) \
    asm volatile("mma.sync.aligned.m16n8k16.row.col.f32.f16.f16.f32 " \
                 "{%0,%1,%2,%3}, {%4,%5,%6,%7}, {%8,%9}, {%0,%1,%2,%3};" \
                 : "+f"((d)[0]), "+f"((d)[1]), "+f"((d)[2]), "+f"((d)[3]) \
                 : "r"(a0), "r"(a1), "r"(a2), "r"(a3), "r"(b0), "r"(b1))

// fp16 split: hi = rn-f16(x), lo = rn-f16(x - hi); pack 2 lanes
__device__ __forceinline__ void split2h(float c0, float c1, uint32_t& hi, uint32_t& lo) {
    __half2 h = __floats2half2_rn(c0, c1);
    hi = *(uint32_t*)&h;
    float2 hf = __half22float2(h);
    __half2 l = __floats2half2_rn(c0 - hf.x, c1 - hf.y);
    lo = *(uint32_t*)&l;
}
__device__ __forceinline__ uint32_t pack_h2(float c0, float c1) {
    __half2 h = __floats2half2_rn(c0, c1);
    return *(uint32_t*)&h;
}

// depth-group accumulation (nt literal after unroll -> all indices static)
__device__ __forceinline__ void gacc(int nt, float* g, float e0, float e1, int t) {
    if (nt == 0) {
        g[0] += (t == 0) ? (e0 + e1) : 0.f;
        g[1] += (t == 1) ? e0 : 0.f;
        g[2] += (t == 1) ? e1 : ((t == 2) ? e0 : 0.f);
        g[3] += (t == 2) ? e1 : ((t == 3) ? (e0 + e1) : 0.f);
    } else if (nt == 1) {
        g[3] += (t == 0) ? e0 : 0.f;
        g[4] += (t == 0) ? e1 : (e0 + e1);
    } else if (nt == 2) {
        g[4] += (t == 0) ? e0 : 0.f;
        g[5] += (t == 0) ? e1 : (e0 + e1);
    } else if (nt == 3) {
        g[5] += e0 + e1;
    } else if (nt == 4) {
        g[5] += (t == 0) ? e0 : 0.f;
        g[6] += (t == 0) ? e1 : (e0 + e1);
    } else if (nt <= 7) {
        g[6] += e0 + e1;
    } else if (nt == 8) {
        g[6] += (t == 0) ? e0 : 0.f;
        g[7] += (t == 0) ? e1 : (e0 + e1);
    } else {
        g[7] += e0 + e1;
    }
}
__device__ __forceinline__ float2 samul(int nt, const float* sa, int t) {
    float m0, m1;
    if (nt == 0) {
        m0 = (t == 0) ? sa[0] : (t == 1) ? sa[1] : (t == 2) ? sa[2] : sa[3];
        m1 = (t == 0) ? sa[0] : (t == 1) ? sa[2] : sa[3];
    } else if (nt == 1) { m0 = (t == 0) ? sa[3] : sa[4]; m1 = sa[4]; }
    else if (nt == 2)   { m0 = (t == 0) ? sa[4] : sa[5]; m1 = sa[5]; }
    else if (nt == 3)   { m0 = sa[5]; m1 = sa[5]; }
    else if (nt == 4)   { m0 = (t == 0) ? sa[5] : sa[6]; m1 = sa[6]; }
    else if (nt <= 7)   { m0 = sa[6]; m1 = sa[6]; }
    else if (nt == 8)   { m0 = (t == 0) ? sa[6] : sa[7]; m1 = sa[7]; }
    else                { m0 = sa[7]; m1 = sa[7]; }
    return make_float2(m0, m1);
}

// ---------------- kernel ----------------
__global__ __launch_bounds__(NTH, 2)
void ufa11_kernel(const float* __restrict__ Q, const float* __restrict__ K,
                  const float* __restrict__ V, const float* __restrict__ SW,
                  const float* __restrict__ ST, float* __restrict__ O, CTab tab)
{
    extern __shared__ char AB[];
    const uint32_t ab = s2u(AB);

    __shared__ int   si[129];
    __shared__ float wv[NDEP];
    __shared__ float s128s[128];
    __shared__ float c128s[128];

    const int tid  = threadIdx.x;
    const int w    = tid >> 5;
    const int lane = tid & 31;
    const int b    = blockIdx.y;
    const int q0   = blockIdx.x * QT;
    const float inv_scale = 0.04419417382415922f;  // 1/sqrt(512)

    const int lr = lane & 15;   // ldmatrix row-within-16
    const int lc = lane >> 4;   // ldmatrix k-half
    const int t4 = lane & 3;
    const int rq = lane >> 2;   // fragment row 0..7

    for (int i = tid; i < 129; i += NTH) si[i] = tab.idx[i];
    if (tid == 0) {
        float tmp = ST[0];
        float vvv[NDEP];
        float m = -1e30f;
        #pragma unroll
        for (int d = 0; d < NDEP; ++d) { vvv[d] = SW[d] / tmp; m = fmaxf(m, vvv[d]); }
        float s = 0.f;
        #pragma unroll
        for (int d = 0; d < NDEP; ++d) { vvv[d] = __expf(vvv[d] - m); s += vvv[d]; }
        #pragma unroll
        for (int d = 0; d < NDEP; ++d) wv[d] = vvv[d] / s;
    }
    __syncthreads();

    // ---- raw score column j = 128 (exact fp32) ----
    {
        int q = tid >> 1, h = tid & 1;
        const float4* qr = (const float4*)(Q + ((size_t)b * S_ + q0 + q) * D_ + h * 256);
        const float4* kr = (const float4*)(K + ((size_t)b * S_ + si[128]) * D_ + h * 256);
        float s = 0.f;
        #pragma unroll 8
        for (int i = 0; i < 64; ++i) {
            float4 a = qr[i], c = kr[i];
            s = fmaf(a.x, c.x, s); s = fmaf(a.y, c.y, s);
            s = fmaf(a.z, c.z, s); s = fmaf(a.w, c.w, s);
        }
        s += __shfl_xor_sync(0xffffffffu, s, 1);
        if (h == 0) s128s[q] = s;   // RAW (scaled later in softmax)
    }

    // ================= phase A: S = Q.K^T (raw), single-fp16 mma, double-buffered =================
    float acc[16][4];
    #pragma unroll
    for (int nt = 0; nt < 16; ++nt)
        #pragma unroll
        for (int i = 0; i < 4; ++i)
            acc[nt][i] = 0.f;

    const int frow = tid >> 1;
    const int fkh  = (tid & 1) * 32;

    // fill Q/K single-fp16 tiles for 64-dim chunk ck into buffer s
    auto fillA = [&](int ck, int s) {
        char* qb = AB + s * ABUF;
        char* kb = qb + 16384;
        const float4* Qr = (const float4*)(Q + ((size_t)b * S_ + q0 + frow) * D_ + ck * 64 + fkh);
        const float4* Kr = (const float4*)(K + ((size_t)b * S_ + si[frow]) * D_ + ck * 64 + fkh);
        #pragma unroll
        for (int i = 0; i < 8; ++i) {
            const int k = fkh + i * 4;
            const uint32_t off = frow * 128 + (((k >> 3) ^ (frow & 7)) * 16) + (k & 7) * 2;
            float4 v = Qr[i];
            *(uint2*)(qb + off) = make_uint2(pack_h2(v.x, v.y), pack_h2(v.z, v.w));
            float4 u = Kr[i];
            *(uint2*)(kb + off) = make_uint2(pack_h2(u.x, u.y), pack_h2(u.z, u.w));
        }
    };

    fillA(0, 0);
    __syncthreads();

    #pragma unroll 1
    for (int ck = 0; ck < 8; ++ck) {
        const int s = ck & 1;
        if (ck < 7) fillA(ck + 1, s ^ 1);

        const uint32_t qab = ab + s * ABUF;
        const uint32_t kab = qab + 16384;
        const uint32_t arow = (w * 16 + lr) * 128;
        #pragma unroll
        for (int kk = 0; kk < 4; ++kk) {
            const uint32_t coff = (uint32_t)(((2 * kk + lc) ^ (lr & 7)) * 16);
            uint32_t ah0, ah1, ah2, ah3;
            LDSM4(ah0, ah1, ah2, ah3, qab + arow + coff);
            #pragma unroll
            for (int np = 0; np < 8; ++np) {
                const uint32_t boff = (np * 16 + lr) * 128 + coff;
                uint32_t bh0, bh1, bh2, bh3;
                LDSM4(bh0, bh1, bh2, bh3, kab + boff);
                MMAH(acc[2 * np],     ah0, ah1, ah2, ah3, bh0, bh2);
                MMAH(acc[2 * np + 1], ah0, ah1, ah2, ah3, bh1, bh3);
            }
        }
        __syncthreads();
    }

    // ================= softmax in registers -> C fragments (fp16 hi/lo) in registers =================
    // lane holds rows (w*16 + rq) and (+8); cols j = nt*8 + 2*t4 + {0,1}
    uint32_t chi[8][4], clo[8][4];
    {
        const int qa = w * 16 + rq;
        float mA = s128s[qa], mB = s128s[qa + 8];
        #pragma unroll
        for (int nt = 0; nt < 16; ++nt) {
            mA = fmaxf(mA, fmaxf(acc[nt][0], acc[nt][1]));
            mB = fmaxf(mB, fmaxf(acc[nt][2], acc[nt][3]));
        }
        mA = fmaxf(mA, __shfl_xor_sync(0xffffffffu, mA, 1));
        mA = fmaxf(mA, __shfl_xor_sync(0xffffffffu, mA, 2));
        mB = fmaxf(mB, __shfl_xor_sync(0xffffffffu, mB, 1));
        mB = fmaxf(mB, __shfl_xor_sync(0xffffffffu, mB, 2));

        float gA[NDEP], gB[NDEP];
        #pragma unroll
        for (int d = 0; d < NDEP; ++d) { gA[d] = 0.f; gB[d] = 0.f; }
        #pragma unroll
        for (int nt = 0; nt < 16; ++nt) {
            float e0 = __expf((acc[nt][0] - mA) * inv_scale);
            float e1 = __expf((acc[nt][1] - mA) * inv_scale);
            float e2 = __expf((acc[nt][2] - mB) * inv_scale);
            float e3 = __expf((acc[nt][3] - mB) * inv_scale);
            acc[nt][0] = e0; acc[nt][1] = e1; acc[nt][2] = e2; acc[nt][3] = e3;
            gacc(nt, gA, e0, e1, t4);
            gacc(nt, gB, e2, e3, t4);
        }
        // quad reduction FIRST...
        #pragma unroll
        for (int d = 0; d < NDEP; ++d) {
            gA[d] += __shfl_xor_sync(0xffffffffu, gA[d], 1);
            gA[d] += __shfl_xor_sync(0xffffffffu, gA[d], 2);
            gB[d] += __shfl_xor_sync(0xffffffffu, gB[d], 1);
            gB[d] += __shfl_xor_sync(0xffffffffu, gB[d], 2);
        }
        // ...THEN the (lane-uniform) j=128 term, added exactly once
        const float eA128 = __expf((s128s[qa] - mA) * inv_scale);
        const float eB128 = __expf((s128s[qa + 8] - mB) * inv_scale);
        gA[7] += eA128;
        gB[7] += eB128;

        float ZA = 0.f, ZB = 0.f, saA[NDEP], saB[NDEP];
        #pragma unroll
        for (int d = 0; d < NDEP; ++d) {
            ZA += gA[d]; saA[d] = __fdividef(wv[d], ZA);
            ZB += gB[d]; saB[d] = __fdividef(wv[d], ZB);
        }
        float sA = 0.f, sB = 0.f;
        #pragma unroll
        for (int d = NDEP - 1; d >= 0; --d) {
            sA += saA[d]; saA[d] = sA;
            sB += saB[d]; saB[d] = sB;
        }
        if (t4 == 0) {
            c128s[qa]     = eA128 * saA[7];
            c128s[qa + 8] = eB128 * saB[7];
        }
        // coefficients -> fp16 mma A-fragment registers (acc layout == A-frag layout)
        #pragma unroll
        for (int nt = 0; nt < 16; ++nt) {
            float2 muA = samul(nt, saA, t4);
            float2 muB = samul(nt, saB, t4);
            const int kk = nt >> 1;
            const int o  = (nt & 1) * 2;
            split2h(acc[nt][0] * muA.x, acc[nt][1] * muA.y, chi[kk][o],     clo[kk][o]);
            split2h(acc[nt][2] * muB.x, acc[nt][3] * muB.y, chi[kk][o + 1], clo[kk][o + 1]);
        }
    }

    // ================= phase B: O = C . V  (8 d-chunks of 64, double-buffered fp16 V) =================
    // V tiles stored row-major [j][d] (pitch 144B), single fp16, consumed via ldmatrix.trans.
    auto fillV = [&](int dc, int s) {
        const int fj = tid >> 1;            // key row 0..127
        const int fh = tid & 1;             // 32-dim half
        char* vb = AB + s * VBUF;
        const float4* Vr = (const float4*)(V + ((size_t)b * S_ + si[fj]) * D_ + dc * 64 + fh * 32);
        #pragma unroll
        for (int i = 0; i < 8; ++i) {
            float4 v = Vr[i];
            const uint32_t off = fj * VPITCH + fh * 64 + i * 8;
            *(uint2*)(vb + off) = make_uint2(pack_h2(v.x, v.y), pack_h2(v.z, v.w));
        }
    };

    const int si128 = si[128];
    __syncthreads();   // phase-A tiles dead before V overlays them
    fillV(0, 0);
    __syncthreads();

    #pragma unroll 1
    for (int dc = 0; dc < 8; ++dc) {
        const int s = dc & 1;
        if (dc < 7) fillV(dc + 1, s ^ 1);

        float oa[8][4];
        #pragma unroll
        for (int nt = 0; nt < 8; ++nt)
            #pragma unroll
            for (int i = 0; i < 4; ++i)
                oa[nt][i] = 0.f;

        const uint32_t vbase = ab + s * VBUF + (lane & 15) * VPITCH + (lane >> 4) * 16;
        #pragma unroll
        for (int kk = 0; kk < 8; ++kk) {
            #pragma unroll
            for (int ng = 0; ng < 4; ++ng) {
                const uint32_t a0 = vbase + kk * (16 * VPITCH) + ng * 32;
                uint32_t vh0, vh1, vh2, vh3;
                LDSM4T(vh0, vh1, vh2, vh3, a0);
                MMAH(oa[2 * ng],     chi[kk][0], chi[kk][1], chi[kk][2], chi[kk][3], vh0, vh1);
                MMAH(oa[2 * ng],     clo[kk][0], clo[kk][1], clo[kk][2], clo[kk][3], vh0, vh1);
                MMAH(oa[2 * ng + 1], chi[kk][0], chi[kk][1], chi[kk][2], chi[kk][3], vh2, vh3);
                MMAH(oa[2 * ng + 1], clo[kk][0], clo[kk][1], clo[kk][2], clo[kk][3], vh2, vh3);
            }
        }

        // epilogue: add key-128 term (fp32 exact), store O
        {
            const int qa = w * 16 + rq;
            const float cA = c128s[qa], cB = c128s[qa + 8];
            const float* v128 = V + ((size_t)b * S_ + si128) * D_ + dc * 64;
            float* OA = O + ((size_t)b * S_ + q0 + qa) * D_ + dc * 64;
            float* OB = OA + 8 * D_;
            #pragma unroll
            for (int nt = 0; nt < 8; ++nt) {
                const int nc = nt * 8 + 2 * t4;
                const float2 vv = *(const float2*)(v128 + nc);
                *(float2*)(OA + nc) = make_float2(oa[nt][0] + cA * vv.x, oa[nt][1] + cA * vv.y);
                *(float2*)(OB + nc) = make_float2(oa[nt][2] + cB * vv.x, oa[nt][3] + cB * vv.y);
            }
        }
        __syncthreads();
    }
}

// ---------------- launch ----------------
extern "C" void kernel_launch(void* const* d_in, const int* in_sizes, int n_in,
                              void* d_out, int out_size)
{
    const float* Q  = (const float*)d_in[0];
    const float* K  = (const float*)d_in[1];
    const float* V  = (const float*)d_in[2];
    // d_in[3] = t (unused by the reference)
    const float* SW = (const float*)d_in[4];
    const float* ST = (const float*)d_in[5];
    float* O = (float*)d_out;

    cudaFuncSetAttribute(ufa11_kernel, cudaFuncAttributeMaxDynamicSharedMemorySize, DYN_BYTES);

    dim3 grid(S_ / QT, B_);
    ufa11_kernel<<<grid, NTH, DYN_BYTES>>>(Q, K, V, SW, ST, O, g_tab);
}

// round 13
// speedup vs baseline: 1.3462x; 1.0347x over previous
#include <cuda_runtime.h>
#include <cuda_bf16.h>
#include <cuda_fp16.h>
#include <cstdint>
#include <vector>
#include <algorithm>

// ---------------- problem constants ----------------
#define B_    8
#define S_    4096
#define D_    512
#define QT    128
#define NTH   128        // 4 warps, 32 q-rows each
#define NDEP  8

// smem byte offsets (dynamic smem base AB)
// phase A: single-fp16 Q/K tiles (128 rows x 128B, XOR-swizzled), double buffered
#define ABUF     32768
// phase B: V tiles [128 j][72 fp16] pitch 144B (single fp16), double buffered (overlays A)
#define VPITCH   144
#define VBUF     18432
#define DYN_BYTES 65536

// ---------------- host-side Cantor table (keys sorted by (dmin, idx)) ----------------
struct CTab { int idx[129]; };
static CTab g_tab;

static bool build_tables() {
    std::vector<std::vector<long long>> idxd;
    auto to_idx = [](const std::vector<double>& p) {
        std::vector<long long> v;
        for (double x : p) v.push_back((long long)(x * 4095.0));
        std::sort(v.begin(), v.end());
        v.erase(std::unique(v.begin(), v.end()), v.end());
        return v;
    };
    std::vector<double> prev = {0.0, 1.0};
    idxd.push_back(to_idx(prev));
    for (int d = 1; d < NDEP; ++d) {
        std::vector<double> nw;
        for (size_t i = 0; i + 1 < prev.size(); ++i) {
            double left = prev[i], right = prev[i + 1];
            double third = (right - left) / 3.0;
            nw.push_back(left);
            nw.push_back(left + third);
        }
        nw.push_back(prev.back());
        prev.swap(nw);
        idxd.push_back(to_idx(prev));
    }
    const std::vector<long long>& uni = idxd[NDEP - 1];   // 129 keys (nested union)
    int nu = (int)uni.size();
    std::vector<std::pair<int, long long>> keys;
    for (int j = 0; j < nu; ++j) {
        int dm = NDEP - 1;
        for (int d = 0; d < NDEP; ++d)
            if (std::binary_search(idxd[d].begin(), idxd[d].end(), uni[j])) { dm = d; break; }
        keys.push_back({dm, uni[j]});
    }
    std::sort(keys.begin(), keys.end());
    for (int j = 0; j < nu && j < 129; ++j) g_tab.idx[j] = (int)keys[j].second;
    return true;
}
static bool g_built = build_tables();
// sorted-slot depth groups: bnd = {0,2,3,5,9,17,33,65,129}

// ---------------- helpers ----------------
__device__ __forceinline__ uint32_t s2u(const void* p) {
    uint32_t a;
    asm("{ .reg .u64 t; cvta.to.shared.u64 t, %1; cvt.u32.u64 %0, t; }" : "=r"(a) : "l"(p));
    return a;
}

#define LDSM4(r0, r1, r2, r3, addr) \
    asm volatile("ldmatrix.sync.aligned.m8n8.x4.shared.b16 {%0,%1,%2,%3}, [%4];" \
                 : "=r"(r0), "=r"(r1), "=r"(r2), "=r"(r3) : "r"(addr))

#define LDSM4T(r0, r1, r2, r3, addr) \
    asm volatile("ldmatrix.sync.aligned.m8n8.x4.trans.shared.b16 {%0,%1,%2,%3}, [%4];" \
                 : "=r"(r0), "=r"(r1), "=r"(r2), "=r"(r3) : "r"(addr))

#define MMAH(d, a0, a1, a2, a3, b0, b1) \
    asm volatile("mma.sync.aligned.m16n8k16.row.col.f32.f16.f16.f32 " \
                 "{%0,%1,%2,%3}, {%4,%5,%6,%7}, {%8,%9}, {%0,%1,%2,%3};" \
                 : "+f"((d)[0]), "+f"((d)[1]), "+f"((d)[2]), "+f"((d)[3]) \
                 : "r"(a0), "r"(a1), "r"(a2), "r"(a3), "r"(b0), "r"(b1))

// fp16 split: hi = rn-f16(x), lo = rn-f16(x - hi); pack 2 lanes
__device__ __forceinline__ void split2h(float c0, float c1, uint32_t& hi, uint32_t& lo) {
    __half2 h = __floats2half2_rn(c0, c1);
    hi = *(uint32_t*)&h;
    float2 hf = __half22float2(h);
    __half2 l = __floats2half2_rn(c0 - hf.x, c1 - hf.y);
    lo = *(uint32_t*)&l;
}
__device__ __forceinline__ uint32_t pack_h2(float c0, float c1) {
    __half2 h = __floats2half2_rn(c0, c1);
    return *(uint32_t*)&h;
}

// depth-group accumulation (nt literal after unroll -> all indices static)
__device__ __forceinline__ void gacc(int nt, float* g, float e0, float e1, int t) {
    if (nt == 0) {
        g[0] += (t == 0) ? (e0 + e1) : 0.f;
        g[1] += (t == 1) ? e0 : 0.f;
        g[2] += (t == 1) ? e1 : ((t == 2) ? e0 : 0.f);
        g[3] += (t == 2) ? e1 : ((t == 3) ? (e0 + e1) : 0.f);
    } else if (nt == 1) {
        g[3] += (t == 0) ? e0 : 0.f;
        g[4] += (t == 0) ? e1 : (e0 + e1);
    } else if (nt == 2) {
        g[4] += (t == 0) ? e0 : 0.f;
        g[5] += (t == 0) ? e1 : (e0 + e1);
    } else if (nt == 3) {
        g[5] += e0 + e1;
    } else if (nt == 4) {
        g[5] += (t == 0) ? e0 : 0.f;
        g[6] += (t == 0) ? e1 : (e0 + e1);
    } else if (nt <= 7) {
        g[6] += e0 + e1;
    } else if (nt == 8) {
        g[6] += (t == 0) ? e0 : 0.f;
        g[7] += (t == 0) ? e1 : (e0 + e1);
    } else {
        g[7] += e0 + e1;
    }
}
__device__ __forceinline__ float2 samul(int nt, const float* sa, int t) {
    float m0, m1;
    if (nt == 0) {
        m0 = (t == 0) ? sa[0] : (t == 1) ? sa[1] : (t == 2) ? sa[2] : sa[3];
        m1 = (t == 0) ? sa[0] : (t == 1) ? sa[2] : sa[3];
    } else if (nt == 1) { m0 = (t == 0) ? sa[3] : sa[4]; m1 = sa[4]; }
    else if (nt == 2)   { m0 = (t == 0) ? sa[4] : sa[5]; m1 = sa[5]; }
    else if (nt == 3)   { m0 = sa[5]; m1 = sa[5]; }
    else if (nt == 4)   { m0 = (t == 0) ? sa[5] : sa[6]; m1 = sa[6]; }
    else if (nt <= 7)   { m0 = sa[6]; m1 = sa[6]; }
    else if (nt == 8)   { m0 = (t == 0) ? sa[6] : sa[7]; m1 = sa[7]; }
    else                { m0 = sa[7]; m1 = sa[7]; }
    return make_float2(m0, m1);
}

// ---------------- kernel ----------------
__global__ __launch_bounds__(NTH, 2)
void ufa12_kernel(const float* __restrict__ Q, const float* __restrict__ K,
                  const float* __restrict__ V, const float* __restrict__ SW,
                  const float* __restrict__ ST, float* __restrict__ O, CTab tab)
{
    extern __shared__ char AB[];
    const uint32_t ab = s2u(AB);

    __shared__ int   si[129];
    __shared__ float wv[NDEP];
    __shared__ float s128s[128];
    __shared__ float c128s[128];

    const int tid  = threadIdx.x;
    const int w    = tid >> 5;      // 0..3
    const int lane = tid & 31;
    const int b    = blockIdx.y;
    const int q0   = blockIdx.x * QT;
    const float inv_scale = 0.04419417382415922f;  // 1/sqrt(512)

    const int lr = lane & 15;
    const int lc = lane >> 4;
    const int t4 = lane & 3;
    const int rq = lane >> 2;

    for (int i = tid; i < 129; i += NTH) si[i] = tab.idx[i];
    if (tid == 0) {
        float tmp = ST[0];
        float vvv[NDEP];
        float m = -1e30f;
        #pragma unroll
        for (int d = 0; d < NDEP; ++d) { vvv[d] = SW[d] / tmp; m = fmaxf(m, vvv[d]); }
        float s = 0.f;
        #pragma unroll
        for (int d = 0; d < NDEP; ++d) { vvv[d] = __expf(vvv[d] - m); s += vvv[d]; }
        #pragma unroll
        for (int d = 0; d < NDEP; ++d) wv[d] = vvv[d] / s;
    }
    __syncthreads();

    // ---- raw score column j = 128 (exact fp32), two row-blocks ----
    #pragma unroll
    for (int r2 = 0; r2 < 2; ++r2) {
        int q = (tid >> 1) + r2 * 64, h = tid & 1;
        const float4* qr = (const float4*)(Q + ((size_t)b * S_ + q0 + q) * D_ + h * 256);
        const float4* kr = (const float4*)(K + ((size_t)b * S_ + si[128]) * D_ + h * 256);
        float s = 0.f;
        #pragma unroll 8
        for (int i = 0; i < 64; ++i) {
            float4 a = qr[i], c = kr[i];
            s = fmaf(a.x, c.x, s); s = fmaf(a.y, c.y, s);
            s = fmaf(a.z, c.z, s); s = fmaf(a.w, c.w, s);
        }
        s += __shfl_xor_sync(0xffffffffu, s, 1);
        if (h == 0) s128s[q] = s;
    }

    // ================= phase A: S = Q.K^T (raw), single-fp16 mma, double-buffered =================
    // warp owns rows [32w, 32w+32) x all 128 cols: acc[mt][nt][4], mt=rows +16*mt
    float acc[2][16][4];
    #pragma unroll
    for (int mt = 0; mt < 2; ++mt)
        #pragma unroll
        for (int nt = 0; nt < 16; ++nt)
            #pragma unroll
            for (int i = 0; i < 4; ++i)
                acc[mt][nt][i] = 0.f;

    auto fillA = [&](int ck, int s) {
        char* qb = AB + s * ABUF;
        char* kb = qb + 16384;
        const int fr  = tid >> 1;
        const int fkh = (tid & 1) * 32;
        #pragma unroll
        for (int r2 = 0; r2 < 2; ++r2) {
            const int frow = fr + r2 * 64;
            const float4* Qr = (const float4*)(Q + ((size_t)b * S_ + q0 + frow) * D_ + ck * 64 + fkh);
            const float4* Kr = (const float4*)(K + ((size_t)b * S_ + si[frow]) * D_ + ck * 64 + fkh);
            #pragma unroll
            for (int i = 0; i < 8; ++i) {
                const int k = fkh + i * 4;
                const uint32_t off = frow * 128 + (((k >> 3) ^ (frow & 7)) * 16) + (k & 7) * 2;
                float4 v = Qr[i];
                *(uint2*)(qb + off) = make_uint2(pack_h2(v.x, v.y), pack_h2(v.z, v.w));
                float4 u = Kr[i];
                *(uint2*)(kb + off) = make_uint2(pack_h2(u.x, u.y), pack_h2(u.z, u.w));
            }
        }
    };

    fillA(0, 0);
    __syncthreads();

    #pragma unroll 1
    for (int ck = 0; ck < 8; ++ck) {
        const int s = ck & 1;
        if (ck < 7) fillA(ck + 1, s ^ 1);

        const uint32_t qab = ab + s * ABUF;
        const uint32_t kab = qab + 16384;
        #pragma unroll
        for (int kk = 0; kk < 4; ++kk) {
            const uint32_t coff = (uint32_t)(((2 * kk + lc) ^ (lr & 7)) * 16);
            uint32_t ah[2][4];
            #pragma unroll
            for (int mt = 0; mt < 2; ++mt) {
                const uint32_t arow = (uint32_t)((w * 32 + mt * 16 + lr) * 128);
                LDSM4(ah[mt][0], ah[mt][1], ah[mt][2], ah[mt][3], qab + arow + coff);
            }
            #pragma unroll
            for (int np = 0; np < 8; ++np) {
                const uint32_t boff = (uint32_t)((np * 16 + lr) * 128) + coff;
                uint32_t bh0, bh1, bh2, bh3;
                LDSM4(bh0, bh1, bh2, bh3, kab + boff);
                #pragma unroll
                for (int mt = 0; mt < 2; ++mt) {
                    MMAH(acc[mt][2 * np],     ah[mt][0], ah[mt][1], ah[mt][2], ah[mt][3], bh0, bh2);
                    MMAH(acc[mt][2 * np + 1], ah[mt][0], ah[mt][1], ah[mt][2], ah[mt][3], bh1, bh3);
                }
            }
        }
        __syncthreads();
    }

    // ================= softmax in registers -> C fragments (fp16 hi/lo), per mt =================
    uint32_t chi[2][8][4], clo[2][8][4];
    #pragma unroll
    for (int mt = 0; mt < 2; ++mt) {
        const int qa = w * 32 + mt * 16 + rq;
        float mA = s128s[qa], mB = s128s[qa + 8];
        #pragma unroll
        for (int nt = 0; nt < 16; ++nt) {
            mA = fmaxf(mA, fmaxf(acc[mt][nt][0], acc[mt][nt][1]));
            mB = fmaxf(mB, fmaxf(acc[mt][nt][2], acc[mt][nt][3]));
        }
        mA = fmaxf(mA, __shfl_xor_sync(0xffffffffu, mA, 1));
        mA = fmaxf(mA, __shfl_xor_sync(0xffffffffu, mA, 2));
        mB = fmaxf(mB, __shfl_xor_sync(0xffffffffu, mB, 1));
        mB = fmaxf(mB, __shfl_xor_sync(0xffffffffu, mB, 2));

        float gA[NDEP], gB[NDEP];
        #pragma unroll
        for (int d = 0; d < NDEP; ++d) { gA[d] = 0.f; gB[d] = 0.f; }
        #pragma unroll
        for (int nt = 0; nt < 16; ++nt) {
            float e0 = __expf((acc[mt][nt][0] - mA) * inv_scale);
            float e1 = __expf((acc[mt][nt][1] - mA) * inv_scale);
            float e2 = __expf((acc[mt][nt][2] - mB) * inv_scale);
            float e3 = __expf((acc[mt][nt][3] - mB) * inv_scale);
            acc[mt][nt][0] = e0; acc[mt][nt][1] = e1;
            acc[mt][nt][2] = e2; acc[mt][nt][3] = e3;
            gacc(nt, gA, e0, e1, t4);
            gacc(nt, gB, e2, e3, t4);
        }
        // quad reduction FIRST...
        #pragma unroll
        for (int d = 0; d < NDEP; ++d) {
            gA[d] += __shfl_xor_sync(0xffffffffu, gA[d], 1);
            gA[d] += __shfl_xor_sync(0xffffffffu, gA[d], 2);
            gB[d] += __shfl_xor_sync(0xffffffffu, gB[d], 1);
            gB[d] += __shfl_xor_sync(0xffffffffu, gB[d], 2);
        }
        // ...THEN the (lane-uniform) j=128 term, added exactly once
        const float eA128 = __expf((s128s[qa] - mA) * inv_scale);
        const float eB128 = __expf((s128s[qa + 8] - mB) * inv_scale);
        gA[7] += eA128;
        gB[7] += eB128;

        float ZA = 0.f, ZB = 0.f, saA[NDEP], saB[NDEP];
        #pragma unroll
        for (int d = 0; d < NDEP; ++d) {
            ZA += gA[d]; saA[d] = __fdividef(wv[d], ZA);
            ZB += gB[d]; saB[d] = __fdividef(wv[d], ZB);
        }
        float sA = 0.f, sB = 0.f;
        #pragma unroll
        for (int d = NDEP - 1; d >= 0; --d) {
            sA += saA[d]; saA[d] = sA;
            sB += saB[d]; saB[d] = sB;
        }
        if (t4 == 0) {
            c128s[qa]     = eA128 * saA[7];
            c128s[qa + 8] = eB128 * saB[7];
        }
        #pragma unroll
        for (int nt = 0; nt < 16; ++nt) {
            float2 muA = samul(nt, saA, t4);
            float2 muB = samul(nt, saB, t4);
            const int kk = nt >> 1;
            const int o  = (nt & 1) * 2;
            split2h(acc[mt][nt][0] * muA.x, acc[mt][nt][1] * muA.y, chi[mt][kk][o],     clo[mt][kk][o]);
            split2h(acc[mt][nt][2] * muB.x, acc[mt][nt][3] * muB.y, chi[mt][kk][o + 1], clo[mt][kk][o + 1]);
        }
    }

    // ================= phase B: O = C . V  (8 d-chunks of 64, double-buffered fp16 V) =================
    auto fillV = [&](int dc, int s) {
        char* vb = AB + s * VBUF;
        const int fr = tid >> 1;
        const int fh = tid & 1;
        #pragma unroll
        for (int r2 = 0; r2 < 2; ++r2) {
            const int fj = fr + r2 * 64;
            const float4* Vr = (const float4*)(V + ((size_t)b * S_ + si[fj]) * D_ + dc * 64 + fh * 32);
            #pragma unroll
            for (int i = 0; i < 8; ++i) {
                float4 v = Vr[i];
                const uint32_t off = fj * VPITCH + fh * 64 + i * 8;
                *(uint2*)(vb + off) = make_uint2(pack_h2(v.x, v.y), pack_h2(v.z, v.w));
            }
        }
    };

    const int si128 = si[128];
    __syncthreads();   // phase-A tiles dead before V overlays them
    fillV(0, 0);
    __syncthreads();

    #pragma unroll 1
    for (int dc = 0; dc < 8; ++dc) {
        const int s = dc & 1;
        if (dc < 7) fillV(dc + 1, s ^ 1);

        float oa[2][8][4];
        #pragma unroll
        for (int mt = 0; mt < 2; ++mt)
            #pragma unroll
            for (int nt = 0; nt < 8; ++nt)
                #pragma unroll
                for (int i = 0; i < 4; ++i)
                    oa[mt][nt][i] = 0.f;

        const uint32_t vbase = ab + s * VBUF + (lane & 15) * VPITCH + (lane >> 4) * 16;
        #pragma unroll
        for (int kk = 0; kk < 8; ++kk) {
            #pragma unroll
            for (int ng = 0; ng < 4; ++ng) {
                const uint32_t a0 = vbase + kk * (16 * VPITCH) + ng * 32;
                uint32_t vh0, vh1, vh2, vh3;
                LDSM4T(vh0, vh1, vh2, vh3, a0);
                #pragma unroll
                for (int mt = 0; mt < 2; ++mt) {
                    MMAH(oa[mt][2 * ng],     chi[mt][kk][0], chi[mt][kk][1], chi[mt][kk][2], chi[mt][kk][3], vh0, vh1);
                    MMAH(oa[mt][2 * ng],     clo[mt][kk][0], clo[mt][kk][1], clo[mt][kk][2], clo[mt][kk][3], vh0, vh1);
                    MMAH(oa[mt][2 * ng + 1], chi[mt][kk][0], chi[mt][kk][1], chi[mt][kk][2], chi[mt][kk][3], vh2, vh3);
                    MMAH(oa[mt][2 * ng + 1], clo[mt][kk][0], clo[mt][kk][1], clo[mt][kk][2], clo[mt][kk][3], vh2, vh3);
                }
            }
        }

        // epilogue: add key-128 term (fp32 exact), store O
        {
            const float* v128 = V + ((size_t)b * S_ + si128) * D_ + dc * 64;
            #pragma unroll
            for (int mt = 0; mt < 2; ++mt) {
                const int qa = w * 32 + mt * 16 + rq;
                const float cA = c128s[qa], cB = c128s[qa + 8];
                float* OA = O + ((size_t)b * S_ + q0 + qa) * D_ + dc * 64;
                float* OB = OA + 8 * D_;
                #pragma unroll
                for (int nt = 0; nt < 8; ++nt) {
                    const int nc = nt * 8 + 2 * t4;
                    const float2 vv = *(const float2*)(v128 + nc);
                    *(float2*)(OA + nc) = make_float2(oa[mt][nt][0] + cA * vv.x, oa[mt][nt][1] + cA * vv.y);
                    *(float2*)(OB + nc) = make_float2(oa[mt][nt][2] + cB * vv.x, oa[mt][nt][3] + cB * vv.y);
                }
            }
        }
        __syncthreads();
    }
}

// ---------------- launch ----------------
extern "C" void kernel_launch(void* const* d_in, const int* in_sizes, int n_in,
                              void* d_out, int out_size)
{
    const float* Q  = (const float*)d_in[0];
    const float* K  = (const float*)d_in[1];
    const float* V  = (const float*)d_in[2];
    // d_in[3] = t (unused by the reference)
    const float* SW = (const float*)d_in[4];
    const float* ST = (const float*)d_in[5];
    float* O = (float*)d_out;

    cudaFuncSetAttribute(ufa12_kernel, cudaFuncAttributeMaxDynamicSharedMemorySize, DYN_BYTES);

    dim3 grid(S_ / QT, B_);
    ufa12_kernel<<<grid, NTH, DYN_BYTES>>>(Q, K, V, SW, ST, O, g_tab);
}

// round 14
// speedup vs baseline: 1.5121x; 1.1233x over previous
#include <cuda_runtime.h>
#include <cuda_bf16.h>
#include <cuda_fp16.h>
#include <cstdint>
#include <vector>
#include <algorithm>

// ---------------- problem constants ----------------
#define B_    8
#define S_    4096
#define D_    512
#define QT    128
#define NTH   128        // 4 warps, 32 q-rows each
#define NDEP  8

// smem byte offsets (dynamic smem base AB)
// phase A buffers: Q tile 128x128B (16384) + K tile 144x128B (18432) = 34816 per buffer
#define ABUF     34816
#define KOFF     16384
// phase B: V tiles [128 j][72 fp16] pitch 144B, double buffered (overlays A)
#define VPITCH   144
#define VBUF     18432
#define DYN_BYTES 69632

// ---------------- host-side Cantor table (keys sorted by (dmin, idx)) ----------------
struct CTab { int idx[129]; };
static CTab g_tab;

static bool build_tables() {
    std::vector<std::vector<long long>> idxd;
    auto to_idx = [](const std::vector<double>& p) {
        std::vector<long long> v;
        for (double x : p) v.push_back((long long)(x * 4095.0));
        std::sort(v.begin(), v.end());
        v.erase(std::unique(v.begin(), v.end()), v.end());
        return v;
    };
    std::vector<double> prev = {0.0, 1.0};
    idxd.push_back(to_idx(prev));
    for (int d = 1; d < NDEP; ++d) {
        std::vector<double> nw;
        for (size_t i = 0; i + 1 < prev.size(); ++i) {
            double left = prev[i], right = prev[i + 1];
            double third = (right - left) / 3.0;
            nw.push_back(left);
            nw.push_back(left + third);
        }
        nw.push_back(prev.back());
        prev.swap(nw);
        idxd.push_back(to_idx(prev));
    }
    const std::vector<long long>& uni = idxd[NDEP - 1];   // 129 keys (nested union)
    int nu = (int)uni.size();
    std::vector<std::pair<int, long long>> keys;
    for (int j = 0; j < nu; ++j) {
        int dm = NDEP - 1;
        for (int d = 0; d < NDEP; ++d)
            if (std::binary_search(idxd[d].begin(), idxd[d].end(), uni[j])) { dm = d; break; }
        keys.push_back({dm, uni[j]});
    }
    std::sort(keys.begin(), keys.end());
    for (int j = 0; j < nu && j < 129; ++j) g_tab.idx[j] = (int)keys[j].second;
    return true;
}
static bool g_built = build_tables();
// sorted-slot depth groups: bnd = {0,2,3,5,9,17,33,65,129}

// ---------------- helpers ----------------
__device__ __forceinline__ uint32_t s2u(const void* p) {
    uint32_t a;
    asm("{ .reg .u64 t; cvta.to.shared.u64 t, %1; cvt.u32.u64 %0, t; }" : "=r"(a) : "l"(p));
    return a;
}

#define LDSM4(r0, r1, r2, r3, addr) \
    asm volatile("ldmatrix.sync.aligned.m8n8.x4.shared.b16 {%0,%1,%2,%3}, [%4];" \
                 : "=r"(r0), "=r"(r1), "=r"(r2), "=r"(r3) : "r"(addr))

#define LDSM4T(r0, r1, r2, r3, addr) \
    asm volatile("ldmatrix.sync.aligned.m8n8.x4.trans.shared.b16 {%0,%1,%2,%3}, [%4];" \
                 : "=r"(r0), "=r"(r1), "=r"(r2), "=r"(r3) : "r"(addr))

#define MMAH(d, a0, a1, a2, a3, b0, b1) \
    asm volatile("mma.sync.aligned.m16n8k16.row.col.f32.f16.f16.f32 " \
                 "{%0,%1,%2,%3}, {%4,%5,%6,%7}, {%8,%9}, {%0,%1,%2,%3};" \
                 : "+f"((d)[0]), "+f"((d)[1]), "+f"((d)[2]), "+f"((d)[3]) \
                 : "r"(a0), "r"(a1), "r"(a2), "r"(a3), "r"(b0), "r"(b1))

// fp16 split: hi = rn-f16(x), lo = rn-f16(x - hi); pack 2 lanes
__device__ __forceinline__ void split2h(float c0, float c1, uint32_t& hi, uint32_t& lo) {
    __half2 h = __floats2half2_rn(c0, c1);
    hi = *(uint32_t*)&h;
    float2 hf = __half22float2(h);
    __half2 l = __floats2half2_rn(c0 - hf.x, c1 - hf.y);
    lo = *(uint32_t*)&l;
}
__device__ __forceinline__ uint32_t pack_h2(float c0, float c1) {
    __half2 h = __floats2half2_rn(c0, c1);
    return *(uint32_t*)&h;
}

// depth-group accumulation (nt literal after unroll -> all indices static)
__device__ __forceinline__ void gacc(int nt, float* g, float e0, float e1, int t) {
    if (nt == 0) {
        g[0] += (t == 0) ? (e0 + e1) : 0.f;
        g[1] += (t == 1) ? e0 : 0.f;
        g[2] += (t == 1) ? e1 : ((t == 2) ? e0 : 0.f);
        g[3] += (t == 2) ? e1 : ((t == 3) ? (e0 + e1) : 0.f);
    } else if (nt == 1) {
        g[3] += (t == 0) ? e0 : 0.f;
        g[4] += (t == 0) ? e1 : (e0 + e1);
    } else if (nt == 2) {
        g[4] += (t == 0) ? e0 : 0.f;
        g[5] += (t == 0) ? e1 : (e0 + e1);
    } else if (nt == 3) {
        g[5] += e0 + e1;
    } else if (nt == 4) {
        g[5] += (t == 0) ? e0 : 0.f;
        g[6] += (t == 0) ? e1 : (e0 + e1);
    } else if (nt <= 7) {
        g[6] += e0 + e1;
    } else if (nt == 8) {
        g[6] += (t == 0) ? e0 : 0.f;
        g[7] += (t == 0) ? e1 : (e0 + e1);
    } else {
        g[7] += e0 + e1;
    }
}
__device__ __forceinline__ float2 samul(int nt, const float* sa, int t) {
    float m0, m1;
    if (nt == 0) {
        m0 = (t == 0) ? sa[0] : (t == 1) ? sa[1] : (t == 2) ? sa[2] : sa[3];
        m1 = (t == 0) ? sa[0] : (t == 1) ? sa[2] : sa[3];
    } else if (nt == 1) { m0 = (t == 0) ? sa[3] : sa[4]; m1 = sa[4]; }
    else if (nt == 2)   { m0 = (t == 0) ? sa[4] : sa[5]; m1 = sa[5]; }
    else if (nt == 3)   { m0 = sa[5]; m1 = sa[5]; }
    else if (nt == 4)   { m0 = (t == 0) ? sa[5] : sa[6]; m1 = sa[6]; }
    else if (nt <= 7)   { m0 = sa[6]; m1 = sa[6]; }
    else if (nt == 8)   { m0 = (t == 0) ? sa[6] : sa[7]; m1 = sa[7]; }
    else                { m0 = sa[7]; m1 = sa[7]; }
    return make_float2(m0, m1);
}

// ---------------- kernel ----------------
__global__ __launch_bounds__(NTH, 2)
void ufa13_kernel(const float* __restrict__ Q, const float* __restrict__ K,
                  const float* __restrict__ V, const float* __restrict__ SW,
                  const float* __restrict__ ST, float* __restrict__ O, CTab tab)
{
    extern __shared__ char AB[];
    const uint32_t ab = s2u(AB);

    __shared__ int   si[129];
    __shared__ float wv[NDEP];
    __shared__ float c128s[128];

    const int tid  = threadIdx.x;
    const int w    = tid >> 5;      // 0..3
    const int lane = tid & 31;
    const int b    = blockIdx.y;
    const int q0   = blockIdx.x * QT;
    const float inv_scale = 0.04419417382415922f;  // 1/sqrt(512)

    const int lr = lane & 15;
    const int lc = lane >> 4;
    const int t4 = lane & 3;
    const int rq = lane >> 2;

    for (int i = tid; i < 129; i += NTH) si[i] = tab.idx[i];
    if (tid == 0) {
        float tmp = ST[0];
        float vvv[NDEP];
        float m = -1e30f;
        #pragma unroll
        for (int d = 0; d < NDEP; ++d) { vvv[d] = SW[d] / tmp; m = fmaxf(m, vvv[d]); }
        float s = 0.f;
        #pragma unroll
        for (int d = 0; d < NDEP; ++d) { vvv[d] = __expf(vvv[d] - m); s += vvv[d]; }
        #pragma unroll
        for (int d = 0; d < NDEP; ++d) wv[d] = vvv[d] / s;
    }
    // zero K pad rows 129..143 in BOTH phase-A buffers (never rewritten in phase A)
    for (int i = tid; i < 240; i += NTH) {
        const int buf = i / 120, rem = i % 120;
        const int row = 129 + rem / 8, ch = rem % 8;
        *(uint4*)(AB + buf * ABUF + KOFF + row * 128 + ch * 16) = make_uint4(0, 0, 0, 0);
    }
    __syncthreads();

    const int si128 = si[128];

    // ================= phase A: S = Q.K^T (raw), single-fp16 mma, double-buffered =================
    // warp owns rows [32w, 32w+32) x cols 0..135 (136th..143rd never computed)
    float acc[2][16][4];
    float acc16[2][4];   // score cols 128..135 (only j=128 real)
    #pragma unroll
    for (int mt = 0; mt < 2; ++mt) {
        #pragma unroll
        for (int nt = 0; nt < 16; ++nt)
            #pragma unroll
            for (int i = 0; i < 4; ++i)
                acc[mt][nt][i] = 0.f;
        #pragma unroll
        for (int i = 0; i < 4; ++i) acc16[mt][i] = 0.f;
    }

    auto fillA = [&](int ck, int s) {
        char* qb = AB + s * ABUF;
        char* kb = qb + KOFF;
        const int fr  = tid >> 1;
        const int fkh = (tid & 1) * 32;
        #pragma unroll
        for (int r2 = 0; r2 < 2; ++r2) {
            const int frow = fr + r2 * 64;
            const float4* Qr = (const float4*)(Q + ((size_t)b * S_ + q0 + frow) * D_ + ck * 64 + fkh);
            const float4* Kr = (const float4*)(K + ((size_t)b * S_ + si[frow]) * D_ + ck * 64 + fkh);
            #pragma unroll
            for (int i = 0; i < 8; ++i) {
                const int k = fkh + i * 4;
                const uint32_t off = frow * 128 + (((k >> 3) ^ (frow & 7)) * 16) + (k & 7) * 2;
                float4 v = Qr[i];
                *(uint2*)(qb + off) = make_uint2(pack_h2(v.x, v.y), pack_h2(v.z, v.w));
                float4 u = Kr[i];
                *(uint2*)(kb + off) = make_uint2(pack_h2(u.x, u.y), pack_h2(u.z, u.w));
            }
        }
        // K row 128 (the 129th key); row 128 & 7 == 0 -> identity swizzle
        if (tid < 2) {
            const int fh = tid;
            const float4* Kr = (const float4*)(K + ((size_t)b * S_ + si128) * D_ + ck * 64 + fh * 32);
            #pragma unroll
            for (int i = 0; i < 8; ++i) {
                const int k = fh * 32 + i * 4;
                const uint32_t off = 128 * 128 + ((k >> 3) * 16) + (k & 7) * 2;
                float4 u = Kr[i];
                *(uint2*)(kb + off) = make_uint2(pack_h2(u.x, u.y), pack_h2(u.z, u.w));
            }
        }
    };

    fillA(0, 0);
    __syncthreads();

    #pragma unroll 1
    for (int ck = 0; ck < 8; ++ck) {
        const int s = ck & 1;
        if (ck < 7) fillA(ck + 1, s ^ 1);

        const uint32_t qab = ab + s * ABUF;
        const uint32_t kab = qab + KOFF;
        #pragma unroll
        for (int kk = 0; kk < 4; ++kk) {
            const uint32_t coff = (uint32_t)(((2 * kk + lc) ^ (lr & 7)) * 16);
            uint32_t ah[2][4];
            #pragma unroll
            for (int mt = 0; mt < 2; ++mt) {
                const uint32_t arow = (uint32_t)((w * 32 + mt * 16 + lr) * 128);
                LDSM4(ah[mt][0], ah[mt][1], ah[mt][2], ah[mt][3], qab + arow + coff);
            }
            #pragma unroll
            for (int np = 0; np < 8; ++np) {
                const uint32_t boff = (uint32_t)((np * 16 + lr) * 128) + coff;
                uint32_t bh0, bh1, bh2, bh3;
                LDSM4(bh0, bh1, bh2, bh3, kab + boff);
                #pragma unroll
                for (int mt = 0; mt < 2; ++mt) {
                    MMAH(acc[mt][2 * np],     ah[mt][0], ah[mt][1], ah[mt][2], ah[mt][3], bh0, bh2);
                    MMAH(acc[mt][2 * np + 1], ah[mt][0], ah[mt][1], ah[mt][2], ah[mt][3], bh1, bh3);
                }
            }
            // extra n8 tile: score cols 128..135 (rows 128..143 of K tile)
            {
                const uint32_t boff = (uint32_t)((128 + lr) * 128) + coff;
                uint32_t bh0, bh1, bh2, bh3;
                LDSM4(bh0, bh1, bh2, bh3, kab + boff);
                #pragma unroll
                for (int mt = 0; mt < 2; ++mt)
                    MMAH(acc16[mt], ah[mt][0], ah[mt][1], ah[mt][2], ah[mt][3], bh0, bh2);
            }
        }
        __syncthreads();
    }

    // ================= softmax in registers -> C fragments (fp16 hi/lo), per mt =================
    uint32_t chi[2][8][4], clo[2][8][4];
    #pragma unroll
    for (int mt = 0; mt < 2; ++mt) {
        const int qa = w * 32 + mt * 16 + rq;
        // s128 lives in quad-lane t4==0: element 0 (row rq) / element 2 (row rq+8)
        const float s128A = __shfl_sync(0xffffffffu, acc16[mt][0], lane & ~3);
        const float s128B = __shfl_sync(0xffffffffu, acc16[mt][2], lane & ~3);

        float mA = s128A, mB = s128B;
        #pragma unroll
        for (int nt = 0; nt < 16; ++nt) {
            mA = fmaxf(mA, fmaxf(acc[mt][nt][0], acc[mt][nt][1]));
            mB = fmaxf(mB, fmaxf(acc[mt][nt][2], acc[mt][nt][3]));
        }
        mA = fmaxf(mA, __shfl_xor_sync(0xffffffffu, mA, 1));
        mA = fmaxf(mA, __shfl_xor_sync(0xffffffffu, mA, 2));
        mB = fmaxf(mB, __shfl_xor_sync(0xffffffffu, mB, 1));
        mB = fmaxf(mB, __shfl_xor_sync(0xffffffffu, mB, 2));

        float gA[NDEP], gB[NDEP];
        #pragma unroll
        for (int d = 0; d < NDEP; ++d) { gA[d] = 0.f; gB[d] = 0.f; }
        #pragma unroll
        for (int nt = 0; nt < 16; ++nt) {
            float e0 = __expf((acc[mt][nt][0] - mA) * inv_scale);
            float e1 = __expf((acc[mt][nt][1] - mA) * inv_scale);
            float e2 = __expf((acc[mt][nt][2] - mB) * inv_scale);
            float e3 = __expf((acc[mt][nt][3] - mB) * inv_scale);
            acc[mt][nt][0] = e0; acc[mt][nt][1] = e1;
            acc[mt][nt][2] = e2; acc[mt][nt][3] = e3;
            gacc(nt, gA, e0, e1, t4);
            gacc(nt, gB, e2, e3, t4);
        }
        // quad reduction FIRST...
        #pragma unroll
        for (int d = 0; d < NDEP; ++d) {
            gA[d] += __shfl_xor_sync(0xffffffffu, gA[d], 1);
            gA[d] += __shfl_xor_sync(0xffffffffu, gA[d], 2);
            gB[d] += __shfl_xor_sync(0xffffffffu, gB[d], 1);
            gB[d] += __shfl_xor_sync(0xffffffffu, gB[d], 2);
        }
        // ...THEN the (quad-uniform) j=128 term, added exactly once
        const float eA128 = __expf((s128A - mA) * inv_scale);
        const float eB128 = __expf((s128B - mB) * inv_scale);
        gA[7] += eA128;
        gB[7] += eB128;

        float ZA = 0.f, ZB = 0.f, saA[NDEP], saB[NDEP];
        #pragma unroll
        for (int d = 0; d < NDEP; ++d) {
            ZA += gA[d]; saA[d] = __fdividef(wv[d], ZA);
            ZB += gB[d]; saB[d] = __fdividef(wv[d], ZB);
        }
        float sA = 0.f, sB = 0.f;
        #pragma unroll
        for (int d = NDEP - 1; d >= 0; --d) {
            sA += saA[d]; saA[d] = sA;
            sB += saB[d]; saB[d] = sB;
        }
        if (t4 == 0) {
            c128s[qa]     = eA128 * saA[7];
            c128s[qa + 8] = eB128 * saB[7];
        }
        #pragma unroll
        for (int nt = 0; nt < 16; ++nt) {
            float2 muA = samul(nt, saA, t4);
            float2 muB = samul(nt, saB, t4);
            const int kk = nt >> 1;
            const int o  = (nt & 1) * 2;
            split2h(acc[mt][nt][0] * muA.x, acc[mt][nt][1] * muA.y, chi[mt][kk][o],     clo[mt][kk][o]);
            split2h(acc[mt][nt][2] * muB.x, acc[mt][nt][3] * muB.y, chi[mt][kk][o + 1], clo[mt][kk][o + 1]);
        }
    }

    // ================= phase B: O = C . V  (8 d-chunks of 64, double-buffered fp16 V) =================
    auto fillV = [&](int dc, int s) {
        char* vb = AB + s * VBUF;
        const int fr = tid >> 1;
        const int fh = tid & 1;
        #pragma unroll
        for (int r2 = 0; r2 < 2; ++r2) {
            const int fj = fr + r2 * 64;
            const float4* Vr = (const float4*)(V + ((size_t)b * S_ + si[fj]) * D_ + dc * 64 + fh * 32);
            #pragma unroll
            for (int i = 0; i < 8; ++i) {
                float4 v = Vr[i];
                const uint32_t off = fj * VPITCH + fh * 64 + i * 8;
                *(uint2*)(vb + off) = make_uint2(pack_h2(v.x, v.y), pack_h2(v.z, v.w));
            }
        }
    };

    __syncthreads();   // phase-A tiles dead before V overlays them
    fillV(0, 0);
    __syncthreads();

    #pragma unroll 1
    for (int dc = 0; dc < 8; ++dc) {
        const int s = dc & 1;
        if (dc < 7) fillV(dc + 1, s ^ 1);

        float oa[2][8][4];
        #pragma unroll
        for (int mt = 0; mt < 2; ++mt)
            #pragma unroll
            for (int nt = 0; nt < 8; ++nt)
                #pragma unroll
                for (int i = 0; i < 4; ++i)
                    oa[mt][nt][i] = 0.f;

        const uint32_t vbase = ab + s * VBUF + (lane & 15) * VPITCH + (lane >> 4) * 16;
        #pragma unroll
        for (int kk = 0; kk < 8; ++kk) {
            #pragma unroll
            for (int ng = 0; ng < 4; ++ng) {
                const uint32_t a0 = vbase + kk * (16 * VPITCH) + ng * 32;
                uint32_t vh0, vh1, vh2, vh3;
                LDSM4T(vh0, vh1, vh2, vh3, a0);
                #pragma unroll
                for (int mt = 0; mt < 2; ++mt) {
                    MMAH(oa[mt][2 * ng],     chi[mt][kk][0], chi[mt][kk][1], chi[mt][kk][2], chi[mt][kk][3], vh0, vh1);
                    MMAH(oa[mt][2 * ng],     clo[mt][kk][0], clo[mt][kk][1], clo[mt][kk][2], clo[mt][kk][3], vh0, vh1);
                    MMAH(oa[mt][2 * ng + 1], chi[mt][kk][0], chi[mt][kk][1], chi[mt][kk][2], chi[mt][kk][3], vh2, vh3);
                    MMAH(oa[mt][2 * ng + 1], clo[mt][kk][0], clo[mt][kk][1], clo[mt][kk][2], clo[mt][kk][3], vh2, vh3);
                }
            }
        }

        // epilogue: add key-128 term (fp32), store O
        {
            const float* v128 = V + ((size_t)b * S_ + si128) * D_ + dc * 64;
            #pragma unroll
            for (int mt = 0; mt < 2; ++mt) {
                const int qa = w * 32 + mt * 16 + rq;
                const float cA = c128s[qa], cB = c128s[qa + 8];
                float* OA = O + ((size_t)b * S_ + q0 + qa) * D_ + dc * 64;
                float* OB = OA + 8 * D_;
                #pragma unroll
                for (int nt = 0; nt < 8; ++nt) {
                    const int nc = nt * 8 + 2 * t4;
                    const float2 vv = *(const float2*)(v128 + nc);
                    *(float2*)(OA + nc) = make_float2(oa[mt][nt][0] + cA * vv.x, oa[mt][nt][1] + cA * vv.y);
                    *(float2*)(OB + nc) = make_float2(oa[mt][nt][2] + cB * vv.x, oa[mt][nt][3] + cB * vv.y);
                }
            }
        }
        __syncthreads();
    }
}

// ---------------- launch ----------------
extern "C" void kernel_launch(void* const* d_in, const int* in_sizes, int n_in,
                              void* d_out, int out_size)
{
    const float* Q  = (const float*)d_in[0];
    const float* K  = (const float*)d_in[1];
    const float* V  = (const float*)d_in[2];
    // d_in[3] = t (unused by the reference)
    const float* SW = (const float*)d_in[4];
    const float* ST = (const float*)d_in[5];
    float* O = (float*)d_out;

    cudaFuncSetAttribute(ufa13_kernel, cudaFuncAttributeMaxDynamicSharedMemorySize, DYN_BYTES);

    dim3 grid(S_ / QT, B_);
    ufa13_kernel<<<grid, NTH, DYN_BYTES>>>(Q, K, V, SW, ST, O, g_tab);
}

// round 15
// speedup vs baseline: 1.8256x; 1.2073x over previous
#include <cuda_runtime.h>
#include <cuda_bf16.h>
#include <cuda_fp16.h>
#include <cstdint>
#include <vector>
#include <algorithm>

// ---------------- problem constants ----------------
#define B_    8
#define S_    4096
#define D_    512
#define QT    128
#define NTH   128        // 4 warps, 32 q-rows each
#define NDEP  8

// smem byte offsets (dynamic smem base AB)
// phase A buffers: Q tile 128x128B (16384) + K tile 144x128B (18432) = 34816 per buffer
#define ABUF     34816
#define KOFF     16384
// phase B: V tiles [128 j][72 fp16] pitch 144B, double buffered (overlays A)
#define VPITCH   144
#define VBUF     18432
#define DYN_BYTES 69632

// ---------------- fp16 scratch (device globals; tile-ready layouts) ----------------
// Q: [b][qblock][ck][row 0..127][64 halves]  (XOR-swizzled rows, 128B each)
__device__ __align__(16) __half g_Qs[B_][32][8][128][64];
// K: [b][ck][row 0..128][64 halves] (swizzled; row128 identity)
__device__ __align__(16) __half g_Ks[B_][8][129][64];
// V: [b][dc][row 0..127][64 halves] (plain d-order)
__device__ __align__(16) __half g_Vs[B_][8][128][64];

// ---------------- host-side Cantor table (keys sorted by (dmin, idx)) ----------------
struct CTab { int idx[129]; };
static CTab g_tab;

static bool build_tables() {
    std::vector<std::vector<long long>> idxd;
    auto to_idx = [](const std::vector<double>& p) {
        std::vector<long long> v;
        for (double x : p) v.push_back((long long)(x * 4095.0));
        std::sort(v.begin(), v.end());
        v.erase(std::unique(v.begin(), v.end()), v.end());
        return v;
    };
    std::vector<double> prev = {0.0, 1.0};
    idxd.push_back(to_idx(prev));
    for (int d = 1; d < NDEP; ++d) {
        std::vector<double> nw;
        for (size_t i = 0; i + 1 < prev.size(); ++i) {
            double left = prev[i], right = prev[i + 1];
            double third = (right - left) / 3.0;
            nw.push_back(left);
            nw.push_back(left + third);
        }
        nw.push_back(prev.back());
        prev.swap(nw);
        idxd.push_back(to_idx(prev));
    }
    const std::vector<long long>& uni = idxd[NDEP - 1];   // 129 keys (nested union)
    int nu = (int)uni.size();
    std::vector<std::pair<int, long long>> keys;
    for (int j = 0; j < nu; ++j) {
        int dm = NDEP - 1;
        for (int d = 0; d < NDEP; ++d)
            if (std::binary_search(idxd[d].begin(), idxd[d].end(), uni[j])) { dm = d; break; }
        keys.push_back({dm, uni[j]});
    }
    std::sort(keys.begin(), keys.end());
    for (int j = 0; j < nu && j < 129; ++j) g_tab.idx[j] = (int)keys[j].second;
    return true;
}
static bool g_built = build_tables();
// sorted-slot depth groups: bnd = {0,2,3,5,9,17,33,65,129}

// ---------------- helpers ----------------
__device__ __forceinline__ uint32_t s2u(const void* p) {
    uint32_t a;
    asm("{ .reg .u64 t; cvta.to.shared.u64 t, %1; cvt.u32.u64 %0, t; }" : "=r"(a) : "l"(p));
    return a;
}

#define LDSM4(r0, r1, r2, r3, addr) \
    asm volatile("ldmatrix.sync.aligned.m8n8.x4.shared.b16 {%0,%1,%2,%3}, [%4];" \
                 : "=r"(r0), "=r"(r1), "=r"(r2), "=r"(r3) : "r"(addr))

#define LDSM4T(r0, r1, r2, r3, addr) \
    asm volatile("ldmatrix.sync.aligned.m8n8.x4.trans.shared.b16 {%0,%1,%2,%3}, [%4];" \
                 : "=r"(r0), "=r"(r1), "=r"(r2), "=r"(r3) : "r"(addr))

#define MMAH(d, a0, a1, a2, a3, b0, b1) \
    asm volatile("mma.sync.aligned.m16n8k16.row.col.f32.f16.f16.f32 " \
                 "{%0,%1,%2,%3}, {%4,%5,%6,%7}, {%8,%9}, {%0,%1,%2,%3};" \
                 : "+f"((d)[0]), "+f"((d)[1]), "+f"((d)[2]), "+f"((d)[3]) \
                 : "r"(a0), "r"(a1), "r"(a2), "r"(a3), "r"(b0), "r"(b1))

#define CP16(dst, src) \
    asm volatile("cp.async.cg.shared.global [%0], [%1], 16;" :: "r"(dst), "l"(src) : "memory")
#define CPCOMMIT() asm volatile("cp.async.commit_group;" ::: "memory")
#define CPWAIT0()  asm volatile("cp.async.wait_group 0;" ::: "memory")

// fp16 split: hi = rn-f16(x), lo = rn-f16(x - hi); pack 2 lanes
__device__ __forceinline__ void split2h(float c0, float c1, uint32_t& hi, uint32_t& lo) {
    __half2 h = __floats2half2_rn(c0, c1);
    hi = *(uint32_t*)&h;
    float2 hf = __half22float2(h);
    __half2 l = __floats2half2_rn(c0 - hf.x, c1 - hf.y);
    lo = *(uint32_t*)&l;
}
__device__ __forceinline__ uint32_t pack_h2(float c0, float c1) {
    __half2 h = __floats2half2_rn(c0, c1);
    return *(uint32_t*)&h;
}

// depth-group accumulation (nt literal after unroll -> all indices static)
__device__ __forceinline__ void gacc(int nt, float* g, float e0, float e1, int t) {
    if (nt == 0) {
        g[0] += (t == 0) ? (e0 + e1) : 0.f;
        g[1] += (t == 1) ? e0 : 0.f;
        g[2] += (t == 1) ? e1 : ((t == 2) ? e0 : 0.f);
        g[3] += (t == 2) ? e1 : ((t == 3) ? (e0 + e1) : 0.f);
    } else if (nt == 1) {
        g[3] += (t == 0) ? e0 : 0.f;
        g[4] += (t == 0) ? e1 : (e0 + e1);
    } else if (nt == 2) {
        g[4] += (t == 0) ? e0 : 0.f;
        g[5] += (t == 0) ? e1 : (e0 + e1);
    } else if (nt == 3) {
        g[5] += e0 + e1;
    } else if (nt == 4) {
        g[5] += (t == 0) ? e0 : 0.f;
        g[6] += (t == 0) ? e1 : (e0 + e1);
    } else if (nt <= 7) {
        g[6] += e0 + e1;
    } else if (nt == 8) {
        g[6] += (t == 0) ? e0 : 0.f;
        g[7] += (t == 0) ? e1 : (e0 + e1);
    } else {
        g[7] += e0 + e1;
    }
}
__device__ __forceinline__ float2 samul(int nt, const float* sa, int t) {
    float m0, m1;
    if (nt == 0) {
        m0 = (t == 0) ? sa[0] : (t == 1) ? sa[1] : (t == 2) ? sa[2] : sa[3];
        m1 = (t == 0) ? sa[0] : (t == 1) ? sa[2] : sa[3];
    } else if (nt == 1) { m0 = (t == 0) ? sa[3] : sa[4]; m1 = sa[4]; }
    else if (nt == 2)   { m0 = (t == 0) ? sa[4] : sa[5]; m1 = sa[5]; }
    else if (nt == 3)   { m0 = sa[5]; m1 = sa[5]; }
    else if (nt == 4)   { m0 = (t == 0) ? sa[5] : sa[6]; m1 = sa[6]; }
    else if (nt <= 7)   { m0 = sa[6]; m1 = sa[6]; }
    else if (nt == 8)   { m0 = (t == 0) ? sa[6] : sa[7]; m1 = sa[7]; }
    else                { m0 = sa[7]; m1 = sa[7]; }
    return make_float2(m0, m1);
}

// ---------------- prepass 1: Q fp32 -> fp16 swizzled tiles ----------------
__global__ __launch_bounds__(256)
void prepQ_kernel(const float* __restrict__ Q)
{
    const int qb = blockIdx.x;   // 0..31
    const int b  = blockIdx.y;   // 0..7
    const int tid = threadIdx.x;
    const float* src = Q + ((size_t)b * S_ + qb * QT) * D_;
    #pragma unroll 4
    for (int i = 0; i < 64; ++i) {
        const int idx = i * 256 + tid;        // 0..16383
        const int r   = idx >> 7;             // row 0..127
        const int f4  = idx & 127;            // float4 index in row
        float4 v = ((const float4*)(src + (size_t)r * D_))[f4];
        const int k  = f4 * 4;
        const int ck = k >> 6, kk = k & 63;
        char* dst = (char*)&g_Qs[b][qb][ck][r][0] + (((kk >> 3) ^ (r & 7)) * 16) + (kk & 7) * 2;
        *(uint2*)dst = make_uint2(pack_h2(v.x, v.y), pack_h2(v.z, v.w));
    }
}

// ---------------- prepass 2: gathered K rows (129) + V rows (128) -> fp16 tiles ----------------
__global__ __launch_bounds__(128)
void prepKV_kernel(const float* __restrict__ K, const float* __restrict__ V, CTab tab)
{
    const int j = blockIdx.x;    // 0..128
    const int b = blockIdx.y;    // 0..7
    const int tid = threadIdx.x; // 0..127
    const int row = tab.idx[j];
    const int k  = tid * 4;
    const int ck = k >> 6, kk = k & 63;
    {
        float4 u = *(const float4*)(K + ((size_t)b * S_ + row) * D_ + k);
        char* dst = (char*)&g_Ks[b][ck][j][0] + (((kk >> 3) ^ (j & 7)) * 16) + (kk & 7) * 2;
        *(uint2*)dst = make_uint2(pack_h2(u.x, u.y), pack_h2(u.z, u.w));
    }
    if (j < 128) {
        float4 u = *(const float4*)(V + ((size_t)b * S_ + row) * D_ + k);
        char* dst = (char*)&g_Vs[b][ck][j][0] + kk * 2;
        *(uint2*)dst = make_uint2(pack_h2(u.x, u.y), pack_h2(u.z, u.w));
    }
}

// ---------------- main kernel ----------------
__global__ __launch_bounds__(NTH, 2)
void ufa14_kernel(const float* __restrict__ V, const float* __restrict__ SW,
                  const float* __restrict__ ST, float* __restrict__ O, CTab tab)
{
    extern __shared__ char AB[];
    const uint32_t ab = s2u(AB);

    __shared__ float wv[NDEP];
    __shared__ float c128s[128];

    const int tid  = threadIdx.x;
    const int w    = tid >> 5;      // 0..3
    const int lane = tid & 31;
    const int b    = blockIdx.y;
    const int qb   = blockIdx.x;
    const int q0   = qb * QT;
    const float inv_scale = 0.04419417382415922f;  // 1/sqrt(512)

    const int lr = lane & 15;
    const int lc = lane >> 4;
    const int t4 = lane & 3;
    const int rq = lane >> 2;

    if (tid == 0) {
        float tmp = ST[0];
        float vvv[NDEP];
        float m = -1e30f;
        #pragma unroll
        for (int d = 0; d < NDEP; ++d) { vvv[d] = SW[d] / tmp; m = fmaxf(m, vvv[d]); }
        float s = 0.f;
        #pragma unroll
        for (int d = 0; d < NDEP; ++d) { vvv[d] = __expf(vvv[d] - m); s += vvv[d]; }
        #pragma unroll
        for (int d = 0; d < NDEP; ++d) wv[d] = vvv[d] / s;
    }
    // zero K pad rows 129..143 in BOTH phase-A buffers (cp.async fills only rows 0..128)
    for (int i = tid; i < 240; i += NTH) {
        const int buf = i / 120, rem = i % 120;
        const int row = 129 + rem / 8, ch = rem % 8;
        *(uint4*)(AB + buf * ABUF + KOFF + row * 128 + ch * 16) = make_uint4(0, 0, 0, 0);
    }

    const int si128 = tab.idx[128];

    // ---- cp.async fills ----
    auto fillA = [&](int ck, int s) {
        const uint32_t qdst = ab + s * ABUF;
        const char* qsrc = (const char*)&g_Qs[b][qb][ck][0][0];
        #pragma unroll
        for (int i = 0; i < 8; ++i) {
            const int c = i * 128 + tid;
            CP16(qdst + c * 16, qsrc + c * 16);
        }
        const uint32_t kdst = qdst + KOFF;
        const char* ksrc = (const char*)&g_Ks[b][ck][0][0];
        #pragma unroll
        for (int i = 0; i < 9; ++i) {
            const int c = i * 128 + tid;
            if (c < 1032) CP16(kdst + c * 16, ksrc + c * 16);   // 129 rows x 8 chunks
        }
    };
    auto fillV = [&](int dc, int s) {
        const uint32_t vdst = ab + s * VBUF;
        const char* vsrc = (const char*)&g_Vs[b][dc][0][0];
        #pragma unroll
        for (int i = 0; i < 8; ++i) {
            const int c = i * 128 + tid;        // 128 rows x 8 chunks
            const int j = c >> 3, cc = c & 7;
            CP16(vdst + j * VPITCH + cc * 16, vsrc + c * 16);
        }
    };

    // ================= phase A: S = Q.K^T (raw), single-fp16 mma, double-buffered =================
    float acc[2][16][4];
    float acc16[2][4];   // score cols 128..135 (only j=128 real)
    #pragma unroll
    for (int mt = 0; mt < 2; ++mt) {
        #pragma unroll
        for (int nt = 0; nt < 16; ++nt)
            #pragma unroll
            for (int i = 0; i < 4; ++i)
                acc[mt][nt][i] = 0.f;
        #pragma unroll
        for (int i = 0; i < 4; ++i) acc16[mt][i] = 0.f;
    }

    fillA(0, 0);
    CPCOMMIT();
    CPWAIT0();
    __syncthreads();

    #pragma unroll 1
    for (int ck = 0; ck < 8; ++ck) {
        const int s = ck & 1;
        if (ck < 7) { fillA(ck + 1, s ^ 1); CPCOMMIT(); }

        const uint32_t qab = ab + s * ABUF;
        const uint32_t kab = qab + KOFF;
        #pragma unroll
        for (int kk = 0; kk < 4; ++kk) {
            const uint32_t coff = (uint32_t)(((2 * kk + lc) ^ (lr & 7)) * 16);
            uint32_t ah[2][4];
            #pragma unroll
            for (int mt = 0; mt < 2; ++mt) {
                const uint32_t arow = (uint32_t)((w * 32 + mt * 16 + lr) * 128);
                LDSM4(ah[mt][0], ah[mt][1], ah[mt][2], ah[mt][3], qab + arow + coff);
            }
            #pragma unroll
            for (int np = 0; np < 8; ++np) {
                const uint32_t boff = (uint32_t)((np * 16 + lr) * 128) + coff;
                uint32_t bh0, bh1, bh2, bh3;
                LDSM4(bh0, bh1, bh2, bh3, kab + boff);
                #pragma unroll
                for (int mt = 0; mt < 2; ++mt) {
                    MMAH(acc[mt][2 * np],     ah[mt][0], ah[mt][1], ah[mt][2], ah[mt][3], bh0, bh2);
                    MMAH(acc[mt][2 * np + 1], ah[mt][0], ah[mt][1], ah[mt][2], ah[mt][3], bh1, bh3);
                }
            }
            // extra n8 tile: score cols 128..135 (rows 128..143 of K tile; 129..143 zero)
            {
                const uint32_t boff = (uint32_t)((128 + lr) * 128) + coff;
                uint32_t bh0, bh1, bh2, bh3;
                LDSM4(bh0, bh1, bh2, bh3, kab + boff);
                #pragma unroll
                for (int mt = 0; mt < 2; ++mt)
                    MMAH(acc16[mt], ah[mt][0], ah[mt][1], ah[mt][2], ah[mt][3], bh0, bh2);
            }
        }
        CPWAIT0();
        __syncthreads();
    }

    // V chunk-0 fill overlaps softmax (phase-A buffers partly overwritten: safe, all dead)
    fillV(0, 0);
    CPCOMMIT();

    // ================= softmax in registers -> C fragments (fp16 hi/lo), per mt =================
    uint32_t chi[2][8][4], clo[2][8][4];
    #pragma unroll
    for (int mt = 0; mt < 2; ++mt) {
        const int qa = w * 32 + mt * 16 + rq;
        const float s128A = __shfl_sync(0xffffffffu, acc16[mt][0], lane & ~3);
        const float s128B = __shfl_sync(0xffffffffu, acc16[mt][2], lane & ~3);

        float mA = s128A, mB = s128B;
        #pragma unroll
        for (int nt = 0; nt < 16; ++nt) {
            mA = fmaxf(mA, fmaxf(acc[mt][nt][0], acc[mt][nt][1]));
            mB = fmaxf(mB, fmaxf(acc[mt][nt][2], acc[mt][nt][3]));
        }
        mA = fmaxf(mA, __shfl_xor_sync(0xffffffffu, mA, 1));
        mA = fmaxf(mA, __shfl_xor_sync(0xffffffffu, mA, 2));
        mB = fmaxf(mB, __shfl_xor_sync(0xffffffffu, mB, 1));
        mB = fmaxf(mB, __shfl_xor_sync(0xffffffffu, mB, 2));

        float gA[NDEP], gB[NDEP];
        #pragma unroll
        for (int d = 0; d < NDEP; ++d) { gA[d] = 0.f; gB[d] = 0.f; }
        #pragma unroll
        for (int nt = 0; nt < 16; ++nt) {
            float e0 = __expf((acc[mt][nt][0] - mA) * inv_scale);
            float e1 = __expf((acc[mt][nt][1] - mA) * inv_scale);
            float e2 = __expf((acc[mt][nt][2] - mB) * inv_scale);
            float e3 = __expf((acc[mt][nt][3] - mB) * inv_scale);
            acc[mt][nt][0] = e0; acc[mt][nt][1] = e1;
            acc[mt][nt][2] = e2; acc[mt][nt][3] = e3;
            gacc(nt, gA, e0, e1, t4);
            gacc(nt, gB, e2, e3, t4);
        }
        // quad reduction FIRST...
        #pragma unroll
        for (int d = 0; d < NDEP; ++d) {
            gA[d] += __shfl_xor_sync(0xffffffffu, gA[d], 1);
            gA[d] += __shfl_xor_sync(0xffffffffu, gA[d], 2);
            gB[d] += __shfl_xor_sync(0xffffffffu, gB[d], 1);
            gB[d] += __shfl_xor_sync(0xffffffffu, gB[d], 2);
        }
        // ...THEN the (quad-uniform) j=128 term, added exactly once
        const float eA128 = __expf((s128A - mA) * inv_scale);
        const float eB128 = __expf((s128B - mB) * inv_scale);
        gA[7] += eA128;
        gB[7] += eB128;

        float ZA = 0.f, ZB = 0.f, saA[NDEP], saB[NDEP];
        #pragma unroll
        for (int d = 0; d < NDEP; ++d) {
            ZA += gA[d]; saA[d] = __fdividef(wv[d], ZA);
            ZB += gB[d]; saB[d] = __fdividef(wv[d], ZB);
        }
        float sA = 0.f, sB = 0.f;
        #pragma unroll
        for (int d = NDEP - 1; d >= 0; --d) {
            sA += saA[d]; saA[d] = sA;
            sB += saB[d]; saB[d] = sB;
        }
        if (t4 == 0) {
            c128s[qa]     = eA128 * saA[7];
            c128s[qa + 8] = eB128 * saB[7];
        }
        #pragma unroll
        for (int nt = 0; nt < 16; ++nt) {
            float2 muA = samul(nt, saA, t4);
            float2 muB = samul(nt, saB, t4);
            const int kk = nt >> 1;
            const int o  = (nt & 1) * 2;
            split2h(acc[mt][nt][0] * muA.x, acc[mt][nt][1] * muA.y, chi[mt][kk][o],     clo[mt][kk][o]);
            split2h(acc[mt][nt][2] * muB.x, acc[mt][nt][3] * muB.y, chi[mt][kk][o + 1], clo[mt][kk][o + 1]);
        }
    }

    CPWAIT0();
    __syncthreads();

    // ================= phase B: O = C . V  (8 d-chunks of 64, double-buffered fp16 V) =================
    #pragma unroll 1
    for (int dc = 0; dc < 8; ++dc) {
        const int s = dc & 1;
        if (dc < 7) { fillV(dc + 1, s ^ 1); CPCOMMIT(); }

        float oa[2][8][4];
        #pragma unroll
        for (int mt = 0; mt < 2; ++mt)
            #pragma unroll
            for (int nt = 0; nt < 8; ++nt)
                #pragma unroll
                for (int i = 0; i < 4; ++i)
                    oa[mt][nt][i] = 0.f;

        const uint32_t vbase = ab + s * VBUF + (lane & 15) * VPITCH + (lane >> 4) * 16;
        #pragma unroll
        for (int kk = 0; kk < 8; ++kk) {
            #pragma unroll
            for (int ng = 0; ng < 4; ++ng) {
                const uint32_t a0 = vbase + kk * (16 * VPITCH) + ng * 32;
                uint32_t vh0, vh1, vh2, vh3;
                LDSM4T(vh0, vh1, vh2, vh3, a0);
                #pragma unroll
                for (int mt = 0; mt < 2; ++mt) {
                    MMAH(oa[mt][2 * ng],     chi[mt][kk][0], chi[mt][kk][1], chi[mt][kk][2], chi[mt][kk][3], vh0, vh1);
                    MMAH(oa[mt][2 * ng],     clo[mt][kk][0], clo[mt][kk][1], clo[mt][kk][2], clo[mt][kk][3], vh0, vh1);
                    MMAH(oa[mt][2 * ng + 1], chi[mt][kk][0], chi[mt][kk][1], chi[mt][kk][2], chi[mt][kk][3], vh2, vh3);
                    MMAH(oa[mt][2 * ng + 1], clo[mt][kk][0], clo[mt][kk][1], clo[mt][kk][2], clo[mt][kk][3], vh2, vh3);
                }
            }
        }

        // epilogue: add key-128 term (fp32), store O
        {
            const float* v128 = V + ((size_t)b * S_ + si128) * D_ + dc * 64;
            #pragma unroll
            for (int mt = 0; mt < 2; ++mt) {
                const int qa = w * 32 + mt * 16 + rq;
                const float cA = c128s[qa], cB = c128s[qa + 8];
                float* OA = O + ((size_t)b * S_ + q0 + qa) * D_ + dc * 64;
                float* OB = OA + 8 * D_;
                #pragma unroll
                for (int nt = 0; nt < 8; ++nt) {
                    const int nc = nt * 8 + 2 * t4;
                    const float2 vv = *(const float2*)(v128 + nc);
                    *(float2*)(OA + nc) = make_float2(oa[mt][nt][0] + cA * vv.x, oa[mt][nt][1] + cA * vv.y);
                    *(float2*)(OB + nc) = make_float2(oa[mt][nt][2] + cB * vv.x, oa[mt][nt][3] + cB * vv.y);
                }
            }
        }
        CPWAIT0();
        __syncthreads();
    }
}

// ---------------- launch ----------------
extern "C" void kernel_launch(void* const* d_in, const int* in_sizes, int n_in,
                              void* d_out, int out_size)
{
    const float* Q  = (const float*)d_in[0];
    const float* K  = (const float*)d_in[1];
    const float* V  = (const float*)d_in[2];
    // d_in[3] = t (unused by the reference)
    const float* SW = (const float*)d_in[4];
    const float* ST = (const float*)d_in[5];
    float* O = (float*)d_out;

    // prepass: fp16 conversions into tile-ready scratch
    prepQ_kernel<<<dim3(32, B_), 256>>>(Q);
    prepKV_kernel<<<dim3(129, B_), 128>>>(K, V, g_tab);

    cudaFuncSetAttribute(ufa14_kernel, cudaFuncAttributeMaxDynamicSharedMemorySize, DYN_BYTES);
    dim3 grid(S_ / QT, B_);
    ufa14_kernel<<<grid, NTH, DYN_BYTES>>>(V, SW, ST, O, g_tab);
}

// round 16
// speedup vs baseline: 2.1263x; 1.1647x over previous
#include <cuda_runtime.h>
#include <cuda_bf16.h>
#include <cuda_fp16.h>
#include <cstdint>
#include <vector>
#include <algorithm>

// ---------------- problem constants ----------------
#define B_    8
#define S_    4096
#define D_    512
#define QT    128
#define NTH   128        // 4 warps, 32 q-rows each
#define NDEP  8

// smem byte offsets (dynamic smem base AB)
// phase A buffers: Q tile 128x128B (16384) + K tile 144x128B (18432) = 34816 per buffer
#define ABUF     34816
#define KOFF     16384
// phase B: V tiles [128 j][72 fp16] pitch 144B, double buffered (overlays A)
#define VPITCH   144
#define VBUF     18432
#define DYN_BYTES 69632

// ---------------- fp16 scratch (device globals; tile-ready layouts) ----------------
// Q: [b][qblock][ck][row 0..127][64 halves]  (XOR-swizzled rows, 128B each)
__device__ __align__(16) __half g_Qs[B_][32][8][128][64];
// K: [b][ck][row 0..128][64 halves] (swizzled; row128 identity)
__device__ __align__(16) __half g_Ks[B_][8][129][64];
// V: [b][dc][row 0..127][64 halves] (plain d-order)
__device__ __align__(16) __half g_Vs[B_][8][128][64];

// ---------------- host-side Cantor table (keys sorted by (dmin, idx)) ----------------
struct CTab { int idx[129]; };
static CTab g_tab;

static bool build_tables() {
    std::vector<std::vector<long long>> idxd;
    auto to_idx = [](const std::vector<double>& p) {
        std::vector<long long> v;
        for (double x : p) v.push_back((long long)(x * 4095.0));
        std::sort(v.begin(), v.end());
        v.erase(std::unique(v.begin(), v.end()), v.end());
        return v;
    };
    std::vector<double> prev = {0.0, 1.0};
    idxd.push_back(to_idx(prev));
    for (int d = 1; d < NDEP; ++d) {
        std::vector<double> nw;
        for (size_t i = 0; i + 1 < prev.size(); ++i) {
            double left = prev[i], right = prev[i + 1];
            double third = (right - left) / 3.0;
            nw.push_back(left);
            nw.push_back(left + third);
        }
        nw.push_back(prev.back());
        prev.swap(nw);
        idxd.push_back(to_idx(prev));
    }
    const std::vector<long long>& uni = idxd[NDEP - 1];   // 129 keys (nested union)
    int nu = (int)uni.size();
    std::vector<std::pair<int, long long>> keys;
    for (int j = 0; j < nu; ++j) {
        int dm = NDEP - 1;
        for (int d = 0; d < NDEP; ++d)
            if (std::binary_search(idxd[d].begin(), idxd[d].end(), uni[j])) { dm = d; break; }
        keys.push_back({dm, uni[j]});
    }
    std::sort(keys.begin(), keys.end());
    for (int j = 0; j < nu && j < 129; ++j) g_tab.idx[j] = (int)keys[j].second;
    return true;
}
static bool g_built = build_tables();
// sorted-slot depth groups: bnd = {0,2,3,5,9,17,33,65,129}

// ---------------- helpers ----------------
__device__ __forceinline__ uint32_t s2u(const void* p) {
    uint32_t a;
    asm("{ .reg .u64 t; cvta.to.shared.u64 t, %1; cvt.u32.u64 %0, t; }" : "=r"(a) : "l"(p));
    return a;
}

#define LDSM4(r0, r1, r2, r3, addr) \
    asm volatile("ldmatrix.sync.aligned.m8n8.x4.shared.b16 {%0,%1,%2,%3}, [%4];" \
                 : "=r"(r0), "=r"(r1), "=r"(r2), "=r"(r3) : "r"(addr))

#define LDSM4T(r0, r1, r2, r3, addr) \
    asm volatile("ldmatrix.sync.aligned.m8n8.x4.trans.shared.b16 {%0,%1,%2,%3}, [%4];" \
                 : "=r"(r0), "=r"(r1), "=r"(r2), "=r"(r3) : "r"(addr))

#define MMAH(d, a0, a1, a2, a3, b0, b1) \
    asm volatile("mma.sync.aligned.m16n8k16.row.col.f32.f16.f16.f32 " \
                 "{%0,%1,%2,%3}, {%4,%5,%6,%7}, {%8,%9}, {%0,%1,%2,%3};" \
                 : "+f"((d)[0]), "+f"((d)[1]), "+f"((d)[2]), "+f"((d)[3]) \
                 : "r"(a0), "r"(a1), "r"(a2), "r"(a3), "r"(b0), "r"(b1))

#define CP16(dst, src) \
    asm volatile("cp.async.cg.shared.global [%0], [%1], 16;" :: "r"(dst), "l"(src) : "memory")
#define CPCOMMIT() asm volatile("cp.async.commit_group;" ::: "memory")
#define CPWAIT0()  asm volatile("cp.async.wait_group 0;" ::: "memory")

// fp16 split: hi = rn-f16(x), lo = rn-f16(x - hi); pack 2 lanes
__device__ __forceinline__ void split2h(float c0, float c1, uint32_t& hi, uint32_t& lo) {
    __half2 h = __floats2half2_rn(c0, c1);
    hi = *(uint32_t*)&h;
    float2 hf = __half22float2(h);
    __half2 l = __floats2half2_rn(c0 - hf.x, c1 - hf.y);
    lo = *(uint32_t*)&l;
}
__device__ __forceinline__ uint32_t pack_h2(float c0, float c1) {
    __half2 h = __floats2half2_rn(c0, c1);
    return *(uint32_t*)&h;
}

// depth-group accumulation (nt literal after unroll -> all indices static)
__device__ __forceinline__ void gacc(int nt, float* g, float e0, float e1, int t) {
    if (nt == 0) {
        g[0] += (t == 0) ? (e0 + e1) : 0.f;
        g[1] += (t == 1) ? e0 : 0.f;
        g[2] += (t == 1) ? e1 : ((t == 2) ? e0 : 0.f);
        g[3] += (t == 2) ? e1 : ((t == 3) ? (e0 + e1) : 0.f);
    } else if (nt == 1) {
        g[3] += (t == 0) ? e0 : 0.f;
        g[4] += (t == 0) ? e1 : (e0 + e1);
    } else if (nt == 2) {
        g[4] += (t == 0) ? e0 : 0.f;
        g[5] += (t == 0) ? e1 : (e0 + e1);
    } else if (nt == 3) {
        g[5] += e0 + e1;
    } else if (nt == 4) {
        g[5] += (t == 0) ? e0 : 0.f;
        g[6] += (t == 0) ? e1 : (e0 + e1);
    } else if (nt <= 7) {
        g[6] += e0 + e1;
    } else if (nt == 8) {
        g[6] += (t == 0) ? e0 : 0.f;
        g[7] += (t == 0) ? e1 : (e0 + e1);
    } else {
        g[7] += e0 + e1;
    }
}
__device__ __forceinline__ float2 samul(int nt, const float* sa, int t) {
    float m0, m1;
    if (nt == 0) {
        m0 = (t == 0) ? sa[0] : (t == 1) ? sa[1] : (t == 2) ? sa[2] : sa[3];
        m1 = (t == 0) ? sa[0] : (t == 1) ? sa[2] : sa[3];
    } else if (nt == 1) { m0 = (t == 0) ? sa[3] : sa[4]; m1 = sa[4]; }
    else if (nt == 2)   { m0 = (t == 0) ? sa[4] : sa[5]; m1 = sa[5]; }
    else if (nt == 3)   { m0 = sa[5]; m1 = sa[5]; }
    else if (nt == 4)   { m0 = (t == 0) ? sa[5] : sa[6]; m1 = sa[6]; }
    else if (nt <= 7)   { m0 = sa[6]; m1 = sa[6]; }
    else if (nt == 8)   { m0 = (t == 0) ? sa[6] : sa[7]; m1 = sa[7]; }
    else                { m0 = sa[7]; m1 = sa[7]; }
    return make_float2(m0, m1);
}

// ---------------- prepass 1: Q fp32 -> fp16 swizzled tiles (latency-optimized) ----------------
// grid (256, 8): x = qb*8 + ck; 256 threads; 4 fully-unrolled iterations;
// one 16B store from two contiguous 16B loads (swizzle inverted on read side).
__global__ __launch_bounds__(256)
void prepQ_kernel(const float* __restrict__ Q)
{
    const int qb = blockIdx.x >> 3;
    const int ck = blockIdx.x & 7;
    const int b  = blockIdx.y;
    const int tid = threadIdx.x;
    const float* src = Q + ((size_t)b * S_ + qb * QT) * D_ + ck * 64;
    char* dstb = (char*)&g_Qs[b][qb][ck][0][0];

    float4 a[4], c[4];
    int r[4], p[4];
    #pragma unroll
    for (int i = 0; i < 4; ++i) {
        const int idx = i * 256 + tid;    // 0..1023
        r[i] = idx >> 3;
        p[i] = idx & 7;
        const int k0 = (p[i] ^ (r[i] & 7)) * 8;
        const float* rp = src + (size_t)r[i] * D_ + k0;
        a[i] = *(const float4*)rp;
        c[i] = *(const float4*)(rp + 4);
    }
    #pragma unroll
    for (int i = 0; i < 4; ++i) {
        uint4 o = make_uint4(pack_h2(a[i].x, a[i].y), pack_h2(a[i].z, a[i].w),
                             pack_h2(c[i].x, c[i].y), pack_h2(c[i].z, c[i].w));
        *(uint4*)(dstb + r[i] * 128 + p[i] * 16) = o;
    }
}

// ---------------- prepass 2: gathered K rows (129) + V rows (128) -> fp16 tiles ----------------
__global__ __launch_bounds__(128)
void prepKV_kernel(const float* __restrict__ K, const float* __restrict__ V, CTab tab)
{
    const int j = blockIdx.x;    // 0..128
    const int b = blockIdx.y;    // 0..7
    const int tid = threadIdx.x; // 0..127
    const int row = tab.idx[j];
    const int k  = tid * 4;
    const int ck = k >> 6, kk = k & 63;
    {
        float4 u = *(const float4*)(K + ((size_t)b * S_ + row) * D_ + k);
        char* dst = (char*)&g_Ks[b][ck][j][0] + (((kk >> 3) ^ (j & 7)) * 16) + (kk & 7) * 2;
        *(uint2*)dst = make_uint2(pack_h2(u.x, u.y), pack_h2(u.z, u.w));
    }
    if (j < 128) {
        float4 u = *(const float4*)(V + ((size_t)b * S_ + row) * D_ + k);
        char* dst = (char*)&g_Vs[b][ck][j][0] + kk * 2;
        *(uint2*)dst = make_uint2(pack_h2(u.x, u.y), pack_h2(u.z, u.w));
    }
}

// ---------------- main kernel ----------------
__global__ __launch_bounds__(NTH, 2)
void ufa15_kernel(const float* __restrict__ V, const float* __restrict__ SW,
                  const float* __restrict__ ST, float* __restrict__ O, CTab tab)
{
    extern __shared__ char AB[];
    const uint32_t ab = s2u(AB);

    __shared__ float wv[NDEP];
    __shared__ float c128s[128];

    const int tid  = threadIdx.x;
    const int w    = tid >> 5;      // 0..3
    const int lane = tid & 31;
    const int b    = blockIdx.y;
    const int qb   = blockIdx.x;
    const int q0   = qb * QT;
    const float inv_scale = 0.04419417382415922f;  // 1/sqrt(512)

    const int lr = lane & 15;
    const int lc = lane >> 4;
    const int t4 = lane & 3;
    const int rq = lane >> 2;

    if (tid == 0) {
        float tmp = ST[0];
        float vvv[NDEP];
        float m = -1e30f;
        #pragma unroll
        for (int d = 0; d < NDEP; ++d) { vvv[d] = SW[d] / tmp; m = fmaxf(m, vvv[d]); }
        float s = 0.f;
        #pragma unroll
        for (int d = 0; d < NDEP; ++d) { vvv[d] = __expf(vvv[d] - m); s += vvv[d]; }
        #pragma unroll
        for (int d = 0; d < NDEP; ++d) wv[d] = vvv[d] / s;
    }
    // zero K pad rows 129..143 in BOTH phase-A buffers (cp.async fills only rows 0..128)
    for (int i = tid; i < 240; i += NTH) {
        const int buf = i / 120, rem = i % 120;
        const int row = 129 + rem / 8, ch = rem % 8;
        *(uint4*)(AB + buf * ABUF + KOFF + row * 128 + ch * 16) = make_uint4(0, 0, 0, 0);
    }

    const int si128 = tab.idx[128];

    // ---- cp.async fills ----
    auto fillA = [&](int ck, int s) {
        const uint32_t qdst = ab + s * ABUF;
        const char* qsrc = (const char*)&g_Qs[b][qb][ck][0][0];
        #pragma unroll
        for (int i = 0; i < 8; ++i) {
            const int c = i * 128 + tid;
            CP16(qdst + c * 16, qsrc + c * 16);
        }
        const uint32_t kdst = qdst + KOFF;
        const char* ksrc = (const char*)&g_Ks[b][ck][0][0];
        #pragma unroll
        for (int i = 0; i < 9; ++i) {
            const int c = i * 128 + tid;
            if (c < 1032) CP16(kdst + c * 16, ksrc + c * 16);   // 129 rows x 8 chunks
        }
    };
    auto fillV = [&](int dc, int s) {
        const uint32_t vdst = ab + s * VBUF;
        const char* vsrc = (const char*)&g_Vs[b][dc][0][0];
        #pragma unroll
        for (int i = 0; i < 8; ++i) {
            const int c = i * 128 + tid;        // 128 rows x 8 chunks
            const int j = c >> 3, cc = c & 7;
            CP16(vdst + j * VPITCH + cc * 16, vsrc + c * 16);
        }
    };

    // ================= phase A: S = Q.K^T (raw), single-fp16 mma, double-buffered =================
    float acc[2][16][4];
    float acc16[2][4];   // score cols 128..135 (only j=128 real)
    #pragma unroll
    for (int mt = 0; mt < 2; ++mt) {
        #pragma unroll
        for (int nt = 0; nt < 16; ++nt)
            #pragma unroll
            for (int i = 0; i < 4; ++i)
                acc[mt][nt][i] = 0.f;
        #pragma unroll
        for (int i = 0; i < 4; ++i) acc16[mt][i] = 0.f;
    }

    fillA(0, 0);
    CPCOMMIT();
    CPWAIT0();
    __syncthreads();

    #pragma unroll 1
    for (int ck = 0; ck < 8; ++ck) {
        const int s = ck & 1;
        if (ck < 7) { fillA(ck + 1, s ^ 1); CPCOMMIT(); }

        const uint32_t qab = ab + s * ABUF;
        const uint32_t kab = qab + KOFF;
        #pragma unroll
        for (int kk = 0; kk < 4; ++kk) {
            const uint32_t coff = (uint32_t)(((2 * kk + lc) ^ (lr & 7)) * 16);
            uint32_t ah[2][4];
            #pragma unroll
            for (int mt = 0; mt < 2; ++mt) {
                const uint32_t arow = (uint32_t)((w * 32 + mt * 16 + lr) * 128);
                LDSM4(ah[mt][0], ah[mt][1], ah[mt][2], ah[mt][3], qab + arow + coff);
            }
            #pragma unroll
            for (int np = 0; np < 8; ++np) {
                const uint32_t boff = (uint32_t)((np * 16 + lr) * 128) + coff;
                uint32_t bh0, bh1, bh2, bh3;
                LDSM4(bh0, bh1, bh2, bh3, kab + boff);
                #pragma unroll
                for (int mt = 0; mt < 2; ++mt) {
                    MMAH(acc[mt][2 * np],     ah[mt][0], ah[mt][1], ah[mt][2], ah[mt][3], bh0, bh2);
                    MMAH(acc[mt][2 * np + 1], ah[mt][0], ah[mt][1], ah[mt][2], ah[mt][3], bh1, bh3);
                }
            }
            // extra n8 tile: score cols 128..135 (rows 128..143 of K tile; 129..143 zero)
            {
                const uint32_t boff = (uint32_t)((128 + lr) * 128) + coff;
                uint32_t bh0, bh1, bh2, bh3;
                LDSM4(bh0, bh1, bh2, bh3, kab + boff);
                #pragma unroll
                for (int mt = 0; mt < 2; ++mt)
                    MMAH(acc16[mt], ah[mt][0], ah[mt][1], ah[mt][2], ah[mt][3], bh0, bh2);
            }
        }
        CPWAIT0();
        __syncthreads();
    }

    // V chunk-0 fill overlaps softmax (phase-A buffers partly overwritten: safe, all dead)
    fillV(0, 0);
    CPCOMMIT();

    // ================= softmax in registers -> C fragments (fp16 hi/lo), per mt =================
    uint32_t chi[2][8][4], clo[2][8][4];
    #pragma unroll
    for (int mt = 0; mt < 2; ++mt) {
        const int qa = w * 32 + mt * 16 + rq;
        const float s128A = __shfl_sync(0xffffffffu, acc16[mt][0], lane & ~3);
        const float s128B = __shfl_sync(0xffffffffu, acc16[mt][2], lane & ~3);

        float mA = s128A, mB = s128B;
        #pragma unroll
        for (int nt = 0; nt < 16; ++nt) {
            mA = fmaxf(mA, fmaxf(acc[mt][nt][0], acc[mt][nt][1]));
            mB = fmaxf(mB, fmaxf(acc[mt][nt][2], acc[mt][nt][3]));
        }
        mA = fmaxf(mA, __shfl_xor_sync(0xffffffffu, mA, 1));
        mA = fmaxf(mA, __shfl_xor_sync(0xffffffffu, mA, 2));
        mB = fmaxf(mB, __shfl_xor_sync(0xffffffffu, mB, 1));
        mB = fmaxf(mB, __shfl_xor_sync(0xffffffffu, mB, 2));

        float gA[NDEP], gB[NDEP];
        #pragma unroll
        for (int d = 0; d < NDEP; ++d) { gA[d] = 0.f; gB[d] = 0.f; }
        #pragma unroll
        for (int nt = 0; nt < 16; ++nt) {
            float e0 = __expf((acc[mt][nt][0] - mA) * inv_scale);
            float e1 = __expf((acc[mt][nt][1] - mA) * inv_scale);
            float e2 = __expf((acc[mt][nt][2] - mB) * inv_scale);
            float e3 = __expf((acc[mt][nt][3] - mB) * inv_scale);
            acc[mt][nt][0] = e0; acc[mt][nt][1] = e1;
            acc[mt][nt][2] = e2; acc[mt][nt][3] = e3;
            gacc(nt, gA, e0, e1, t4);
            gacc(nt, gB, e2, e3, t4);
        }
        // quad reduction FIRST...
        #pragma unroll
        for (int d = 0; d < NDEP; ++d) {
            gA[d] += __shfl_xor_sync(0xffffffffu, gA[d], 1);
            gA[d] += __shfl_xor_sync(0xffffffffu, gA[d], 2);
            gB[d] += __shfl_xor_sync(0xffffffffu, gB[d], 1);
            gB[d] += __shfl_xor_sync(0xffffffffu, gB[d], 2);
        }
        // ...THEN the (quad-uniform) j=128 term, added exactly once
        const float eA128 = __expf((s128A - mA) * inv_scale);
        const float eB128 = __expf((s128B - mB) * inv_scale);
        gA[7] += eA128;
        gB[7] += eB128;

        float ZA = 0.f, ZB = 0.f, saA[NDEP], saB[NDEP];
        #pragma unroll
        for (int d = 0; d < NDEP; ++d) {
            ZA += gA[d]; saA[d] = __fdividef(wv[d], ZA);
            ZB += gB[d]; saB[d] = __fdividef(wv[d], ZB);
        }
        float sA = 0.f, sB = 0.f;
        #pragma unroll
        for (int d = NDEP - 1; d >= 0; --d) {
            sA += saA[d]; saA[d] = sA;
            sB += saB[d]; saB[d] = sB;
        }
        if (t4 == 0) {
            c128s[qa]     = eA128 * saA[7];
            c128s[qa + 8] = eB128 * saB[7];
        }
        #pragma unroll
        for (int nt = 0; nt < 16; ++nt) {
            float2 muA = samul(nt, saA, t4);
            float2 muB = samul(nt, saB, t4);
            const int kk = nt >> 1;
            const int o  = (nt & 1) * 2;
            split2h(acc[mt][nt][0] * muA.x, acc[mt][nt][1] * muA.y, chi[mt][kk][o],     clo[mt][kk][o]);
            split2h(acc[mt][nt][2] * muB.x, acc[mt][nt][3] * muB.y, chi[mt][kk][o + 1], clo[mt][kk][o + 1]);
        }
    }

    CPWAIT0();
    __syncthreads();

    // ================= phase B: O = C . V  (8 d-chunks of 64, double-buffered fp16 V) =================
    #pragma unroll 1
    for (int dc = 0; dc < 8; ++dc) {
        const int s = dc & 1;
        if (dc < 7) { fillV(dc + 1, s ^ 1); CPCOMMIT(); }

        float oa[2][8][4];
        #pragma unroll
        for (int mt = 0; mt < 2; ++mt)
            #pragma unroll
            for (int nt = 0; nt < 8; ++nt)
                #pragma unroll
                for (int i = 0; i < 4; ++i)
                    oa[mt][nt][i] = 0.f;

        const uint32_t vbase = ab + s * VBUF + (lane & 15) * VPITCH + (lane >> 4) * 16;
        #pragma unroll
        for (int kk = 0; kk < 8; ++kk) {
            #pragma unroll
            for (int ng = 0; ng < 4; ++ng) {
                const uint32_t a0 = vbase + kk * (16 * VPITCH) + ng * 32;
                uint32_t vh0, vh1, vh2, vh3;
                LDSM4T(vh0, vh1, vh2, vh3, a0);
                #pragma unroll
                for (int mt = 0; mt < 2; ++mt) {
                    MMAH(oa[mt][2 * ng],     chi[mt][kk][0], chi[mt][kk][1], chi[mt][kk][2], chi[mt][kk][3], vh0, vh1);
                    MMAH(oa[mt][2 * ng],     clo[mt][kk][0], clo[mt][kk][1], clo[mt][kk][2], clo[mt][kk][3], vh0, vh1);
                    MMAH(oa[mt][2 * ng + 1], chi[mt][kk][0], chi[mt][kk][1], chi[mt][kk][2], chi[mt][kk][3], vh2, vh3);
                    MMAH(oa[mt][2 * ng + 1], clo[mt][kk][0], clo[mt][kk][1], clo[mt][kk][2], clo[mt][kk][3], vh2, vh3);
                }
            }
        }

        // epilogue: add key-128 term (fp32), store O
        {
            const float* v128 = V + ((size_t)b * S_ + si128) * D_ + dc * 64;
            #pragma unroll
            for (int mt = 0; mt < 2; ++mt) {
                const int qa = w * 32 + mt * 16 + rq;
                const float cA = c128s[qa], cB = c128s[qa + 8];
                float* OA = O + ((size_t)b * S_ + q0 + qa) * D_ + dc * 64;
                float* OB = OA + 8 * D_;
                #pragma unroll
                for (int nt = 0; nt < 8; ++nt) {
                    const int nc = nt * 8 + 2 * t4;
                    const float2 vv = *(const float2*)(v128 + nc);
                    *(float2*)(OA + nc) = make_float2(oa[mt][nt][0] + cA * vv.x, oa[mt][nt][1] + cA * vv.y);
                    *(float2*)(OB + nc) = make_float2(oa[mt][nt][2] + cB * vv.x, oa[mt][nt][3] + cB * vv.y);
                }
            }
        }
        CPWAIT0();
        __syncthreads();
    }
}

// ---------------- launch ----------------
extern "C" void kernel_launch(void* const* d_in, const int* in_sizes, int n_in,
                              void* d_out, int out_size)
{
    const float* Q  = (const float*)d_in[0];
    const float* K  = (const float*)d_in[1];
    const float* V  = (const float*)d_in[2];
    // d_in[3] = t (unused by the reference)
    const float* SW = (const float*)d_in[4];
    const float* ST = (const float*)d_in[5];
    float* O = (float*)d_out;

    // prepass: fp16 conversions into tile-ready scratch
    prepQ_kernel<<<dim3(256, B_), 256>>>(Q);
    prepKV_kernel<<<dim3(129, B_), 128>>>(K, V, g_tab);

    cudaFuncSetAttribute(ufa15_kernel, cudaFuncAttributeMaxDynamicSharedMemorySize, DYN_BYTES);
    dim3 grid(S_ / QT, B_);
    ufa15_kernel<<<grid, NTH, DYN_BYTES>>>(V, SW, ST, O, g_tab);
}